// round 2
// baseline (speedup 1.0000x reference)
#include <cuda_runtime.h>
#include <math.h>

#define N_NODES 20000
#define E_EDGES 320000
#define EN      340000   // E + N self loops
#define IN_DIM  256
#define HID     64
#define NH      4
#define CD      64
#define HC      256      // NH*CD
#define DFF     128
#define NL      4

// ---------------- scratch (module-global device memory; no runtime alloc) ----
__device__ __align__(16) float g_xh[N_NODES * HC];      // per-layer projected features
__device__ __align__(16) float g_as[N_NODES * NH];      // attention src scores
__device__ __align__(16) float g_ad[N_NODES * NH];      // attention dst scores
__device__ __align__(16) float g_alpha[EN * NH];        // per-edge (sorted) softmax weights
__device__ int   g_srt_src[EN];                          // src node per sorted edge slot
__device__ int   g_cnt[N_NODES];
__device__ int   g_off[N_NODES + 1];
__device__ int   g_cur[N_NODES];
__device__ __align__(16) float g_out[N_NODES * HC];     // aggregated messages
__device__ __align__(16) float g_f1[N_NODES * DFF];     // FFN hidden

// ---------------- CSR build ----------------
__global__ void zero_cnt_kernel() {
    int i = blockIdx.x * blockDim.x + threadIdx.x;
    if (i < N_NODES) g_cnt[i] = 0;
}

__global__ void hist_kernel(const int* __restrict__ ei) {
    int i = blockIdx.x * blockDim.x + threadIdx.x;
    if (i >= EN) return;
    int d = (i < E_EDGES) ? ei[E_EDGES + i] : (i - E_EDGES);
    atomicAdd(&g_cnt[d], 1);
}

__global__ void scan_kernel() {
    // single block, 1024 threads, CH=20 elems each
    __shared__ int s[1024];
    const int CH = (N_NODES + 1023) / 1024;   // 20
    int tid = threadIdx.x;
    int base_i = tid * CH;
    int loc[CH];
    int tot = 0;
#pragma unroll
    for (int i = 0; i < CH; i++) {
        int idx = base_i + i;
        int v = (idx < N_NODES) ? g_cnt[idx] : 0;
        loc[i] = tot;
        tot += v;
    }
    s[tid] = tot;
    __syncthreads();
    for (int o = 1; o < 1024; o <<= 1) {
        int v = (tid >= o) ? s[tid - o] : 0;
        __syncthreads();
        s[tid] += v;
        __syncthreads();
    }
    int base = s[tid] - tot;  // exclusive prefix of this thread's chunk
#pragma unroll
    for (int i = 0; i < CH; i++) {
        int idx = base_i + i;
        if (idx < N_NODES) {
            int v = base + loc[i];
            g_off[idx] = v;
            g_cur[idx] = v;
        }
    }
    if (tid == 1023) g_off[N_NODES] = s[1023];
}

__global__ void scatter_kernel(const int* __restrict__ ei) {
    int i = blockIdx.x * blockDim.x + threadIdx.x;
    if (i >= EN) return;
    int s, d;
    if (i < E_EDGES) { s = ei[i]; d = ei[E_EDGES + i]; }
    else             { s = d = i - E_EDGES; }
    int pos = atomicAdd(&g_cur[d], 1);
    g_srt_src[pos] = s;
}

// ---------------- generic small SGEMM (BM=BN=64, BK=16, 4x4 per thread) -----
// EPI: 0 = bias (nullable), 1 = (x+bias)*scale, 2 = gelu(x+bias)
template <int EPI>
__global__ __launch_bounds__(256) void sgemm_kernel(
    const float* __restrict__ A, const float* __restrict__ B,
    const float* __restrict__ bias, float* __restrict__ C,
    int M, int N, int K, float scale)
{
    const int BM = 64, BN = 64, BK = 16;
    __shared__ float As[BK][BM + 1];
    __shared__ float Bs[BK][BN];
    int tid = threadIdx.x;
    int tx = tid & 15, ty = tid >> 4;
    int row0 = blockIdx.y * BM, col0 = blockIdx.x * BN;

    float acc[4][4] = {};
    for (int kk = 0; kk < K; kk += BK) {
#pragma unroll
        for (int i = 0; i < 4; i++) {
            int m = (tid >> 4) + i * 16;
            int k = tid & 15;
            int gm = row0 + m;
            As[k][m] = (gm < M) ? A[(long)gm * K + kk + k] : 0.f;
        }
#pragma unroll
        for (int i = 0; i < 4; i++) {
            int k = (tid >> 6) + i * 4;
            int n = tid & 63;
            Bs[k][n] = B[(long)(kk + k) * N + col0 + n];
        }
        __syncthreads();
#pragma unroll
        for (int k = 0; k < BK; k++) {
            float a[4], b[4];
#pragma unroll
            for (int i = 0; i < 4; i++) a[i] = As[k][ty * 4 + i];
#pragma unroll
            for (int j = 0; j < 4; j++) b[j] = Bs[k][tx * 4 + j];
#pragma unroll
            for (int i = 0; i < 4; i++)
#pragma unroll
                for (int j = 0; j < 4; j++)
                    acc[i][j] = fmaf(a[i], b[j], acc[i][j]);
        }
        __syncthreads();
    }
#pragma unroll
    for (int i = 0; i < 4; i++) {
        int gm = row0 + ty * 4 + i;
        if (gm >= M) continue;
#pragma unroll
        for (int j = 0; j < 4; j++) {
            int gn = col0 + tx * 4 + j;
            float v = acc[i][j];
            if (bias) v += bias[gn];
            if (EPI == 1) v *= scale;
            if (EPI == 2) v = 0.5f * v * (1.0f + erff(v * 0.70710678118654752f));
            C[(long)gm * N + gn] = v;
        }
    }
}

// ---------------- attention scores: a_s/a_d per (node, head) ----------------
__global__ void att_kernel(const float* __restrict__ att_s,
                           const float* __restrict__ att_d)
{
    int gw = (blockIdx.x * blockDim.x + threadIdx.x) >> 5;
    if (gw >= N_NODES) return;
    int lane = threadIdx.x & 31;
    int hh = lane >> 3;
    int sub = lane & 7;
    const float* xr = g_xh + (long)gw * HC + hh * CD;
    const float* ws = att_s + hh * CD;
    const float* wd = att_d + hh * CD;
    float ss = 0.f, sd = 0.f;
#pragma unroll
    for (int j = 0; j < 8; j++) {
        float v = xr[sub + j * 8];
        ss = fmaf(v, ws[sub + j * 8], ss);
        sd = fmaf(v, wd[sub + j * 8], sd);
    }
#pragma unroll
    for (int o = 4; o > 0; o >>= 1) {
        ss += __shfl_down_sync(0xffffffffu, ss, o, 8);
        sd += __shfl_down_sync(0xffffffffu, sd, o, 8);
    }
    if (sub == 0) {
        g_as[gw * 4 + hh] = ss;
        g_ad[gw * 4 + hh] = sd;
    }
}

__device__ __forceinline__ float lrelu(float x) { return x > 0.f ? x : 0.2f * x; }

// ---------------- segment softmax over incoming edges (warp per dst) --------
__global__ void softmax_kernel()
{
    int d = (blockIdx.x * blockDim.x + threadIdx.x) >> 5;
    if (d >= N_NODES) return;
    int lane = threadIdx.x & 31;
    int beg = g_off[d], end = g_off[d + 1];
    float4 ad = *reinterpret_cast<const float4*>(g_ad + d * 4);

    float m0 = -INFINITY, m1 = -INFINITY, m2 = -INFINITY, m3 = -INFINITY;
    for (int p = beg + lane; p < end; p += 32) {
        int s = g_srt_src[p];
        float4 as = *reinterpret_cast<const float4*>(g_as + s * 4);
        m0 = fmaxf(m0, lrelu(as.x + ad.x));
        m1 = fmaxf(m1, lrelu(as.y + ad.y));
        m2 = fmaxf(m2, lrelu(as.z + ad.z));
        m3 = fmaxf(m3, lrelu(as.w + ad.w));
    }
#pragma unroll
    for (int o = 16; o > 0; o >>= 1) {
        m0 = fmaxf(m0, __shfl_xor_sync(0xffffffffu, m0, o));
        m1 = fmaxf(m1, __shfl_xor_sync(0xffffffffu, m1, o));
        m2 = fmaxf(m2, __shfl_xor_sync(0xffffffffu, m2, o));
        m3 = fmaxf(m3, __shfl_xor_sync(0xffffffffu, m3, o));
    }
    float z0 = 0.f, z1 = 0.f, z2 = 0.f, z3 = 0.f;
    for (int p = beg + lane; p < end; p += 32) {
        int s = g_srt_src[p];
        float4 as = *reinterpret_cast<const float4*>(g_as + s * 4);
        float4 ex;
        ex.x = expf(lrelu(as.x + ad.x) - m0);
        ex.y = expf(lrelu(as.y + ad.y) - m1);
        ex.z = expf(lrelu(as.z + ad.z) - m2);
        ex.w = expf(lrelu(as.w + ad.w) - m3);
        *reinterpret_cast<float4*>(g_alpha + (long)p * 4) = ex;
        z0 += ex.x; z1 += ex.y; z2 += ex.z; z3 += ex.w;
    }
#pragma unroll
    for (int o = 16; o > 0; o >>= 1) {
        z0 += __shfl_xor_sync(0xffffffffu, z0, o);
        z1 += __shfl_xor_sync(0xffffffffu, z1, o);
        z2 += __shfl_xor_sync(0xffffffffu, z2, o);
        z3 += __shfl_xor_sync(0xffffffffu, z3, o);
    }
    float r0 = 1.f / (z0 + 1e-16f), r1 = 1.f / (z1 + 1e-16f);
    float r2 = 1.f / (z2 + 1e-16f), r3 = 1.f / (z3 + 1e-16f);
    for (int p = beg + lane; p < end; p += 32) {
        float4 v = *reinterpret_cast<float4*>(g_alpha + (long)p * 4);
        v.x *= r0; v.y *= r1; v.z *= r2; v.w *= r3;
        *reinterpret_cast<float4*>(g_alpha + (long)p * 4) = v;
    }
}

// ---------------- message aggregation (block per dst, no atomics) -----------
__global__ __launch_bounds__(256) void agg_kernel(const float* __restrict__ bc)
{
    int d = blockIdx.x;
    int c = threadIdx.x;           // output channel 0..255
    int hh = c >> 6;
    __shared__ int   s_src[64];
    __shared__ float s_al[64 * 4];
    int beg = g_off[d], end = g_off[d + 1];
    float acc = bc[c];
    for (int base = beg; base < end; base += 64) {
        int nn = min(64, end - base);
        if (c < nn) s_src[c] = g_srt_src[base + c];
        if (c < nn * 4) s_al[c] = g_alpha[(long)base * 4 + c];
        __syncthreads();
#pragma unroll 4
        for (int i = 0; i < nn; i++) {
            acc = fmaf(s_al[i * 4 + hh], g_xh[(long)s_src[i] * HC + c], acc);
        }
        __syncthreads();
    }
    g_out[(long)d * HC + c] = acc;
}

// ---------------- layernorm + residual (warp per node) ----------------------
__global__ void ln_kernel(const float* __restrict__ f,
                          const float* __restrict__ gam,
                          const float* __restrict__ bet,
                          float* __restrict__ h)
{
    int node = (blockIdx.x * blockDim.x + threadIdx.x) >> 5;
    if (node >= N_NODES) return;
    int lane = threadIdx.x & 31;
    float v0 = f[(long)node * HID + lane];
    float v1 = f[(long)node * HID + 32 + lane];
    float s = v0 + v1;
#pragma unroll
    for (int o = 16; o > 0; o >>= 1) s += __shfl_xor_sync(0xffffffffu, s, o);
    float mean = s * (1.f / 64.f);
    float d0 = v0 - mean, d1 = v1 - mean;
    float vv = d0 * d0 + d1 * d1;
#pragma unroll
    for (int o = 16; o > 0; o >>= 1) vv += __shfl_xor_sync(0xffffffffu, vv, o);
    float rstd = rsqrtf(vv * (1.f / 64.f) + 1e-5f);
    h[(long)node * HID + lane]      += d0 * rstd * gam[lane]      + bet[lane];
    h[(long)node * HID + 32 + lane] += d1 * rstd * gam[32 + lane] + bet[32 + lane];
}

// ---------------- driver -----------------------------------------------------
extern "C" void kernel_launch(void* const* d_in, const int* in_sizes, int n_in,
                              void* d_out, int out_size)
{
    const float* x     = (const float*)d_in[0];
    const int*   ei    = (const int*)  d_in[1];
    const float* We    = (const float*)d_in[2];
    const float* be    = (const float*)d_in[3];
    const float* Wc    = (const float*)d_in[4];
    const float* att_s = (const float*)d_in[5];
    const float* att_d = (const float*)d_in[6];
    const float* bc    = (const float*)d_in[7];
    const float* W1    = (const float*)d_in[8];
    const float* b1    = (const float*)d_in[9];
    const float* W2    = (const float*)d_in[10];
    const float* b2    = (const float*)d_in[11];
    const float* lng   = (const float*)d_in[12];
    const float* lnb   = (const float*)d_in[13];
    float* h = (float*)d_out;

    // device scratch pointers (for GEMM args)
    float *p_xh, *p_out, *p_f1;
    cudaGetSymbolAddress((void**)&p_xh,  g_xh);
    cudaGetSymbolAddress((void**)&p_out, g_out);
    cudaGetSymbolAddress((void**)&p_f1,  g_f1);

    // ---- CSR build (once; reused across layers) ----
    zero_cnt_kernel<<<(N_NODES + 255) / 256, 256>>>();
    hist_kernel<<<(EN + 255) / 256, 256>>>(ei);
    scan_kernel<<<1, 1024>>>();
    scatter_kernel<<<(EN + 255) / 256, 256>>>(ei);

    // ---- embed: h = (x @ We + be) * 8 ----
    {
        dim3 grid(HID / 64, (N_NODES + 63) / 64);
        sgemm_kernel<1><<<grid, 256>>>(x, We, be, h, N_NODES, HID, IN_DIM, 8.0f);
    }

    for (int l = 0; l < NL; l++) {
        // xh = h @ Wc[l]
        {
            dim3 grid(HC / 64, (N_NODES + 63) / 64);
            sgemm_kernel<0><<<grid, 256>>>(h, Wc + (long)l * HID * HC, nullptr,
                                           p_xh, N_NODES, HC, HID, 0.f);
        }
        att_kernel<<<(N_NODES * 32 + 255) / 256, 256>>>(att_s + l * NH * CD,
                                                        att_d + l * NH * CD);
        softmax_kernel<<<(N_NODES * 32 + 255) / 256, 256>>>();
        agg_kernel<<<N_NODES, 256>>>(bc + l * HC);
        // f1 = gelu(out @ W1[l] + b1[l])
        {
            dim3 grid(DFF / 64, (N_NODES + 63) / 64);
            sgemm_kernel<2><<<grid, 256>>>(p_out, W1 + (long)l * HC * DFF,
                                           b1 + l * DFF, p_f1, N_NODES, DFF, HC, 0.f);
        }
        // f2 = f1 @ W2[l] + b2[l]  (reuse g_xh as f2 buffer)
        {
            dim3 grid(HID / 64, (N_NODES + 63) / 64);
            sgemm_kernel<0><<<grid, 256>>>(p_f1, W2 + (long)l * DFF * HID,
                                           b2 + l * HID, p_xh, N_NODES, HID, DFF, 0.f);
        }
        // h += layernorm(f2)
        ln_kernel<<<(N_NODES * 32 + 255) / 256, 256>>>(p_xh, lng + l * HID,
                                                       lnb + l * HID, h);
    }
    (void)in_sizes; (void)n_in; (void)out_size;
}

// round 5
// speedup vs baseline: 1.4401x; 1.4401x over previous
#include <cuda_runtime.h>
#include <math.h>
#include <stdint.h>

#define N_NODES 20000
#define E_EDGES 320000
#define EN      340000   // E + N self loops
#define IN_DIM  256
#define HID     64
#define NH      4
#define CD      64
#define HC      256      // NH*CD
#define DFF     128
#define NL      4

// ---------------- scratch (module-global device memory; no runtime alloc) ----
__device__ __align__(16) float g_xh[N_NODES * HC];      // per-layer projected features
__device__ __align__(16) float g_as[N_NODES * NH];      // attention src scores
__device__ __align__(16) float g_ad[N_NODES * NH];      // attention dst scores
__device__ __align__(16) float g_alpha[EN * NH];        // per-edge (sorted) softmax weights
__device__ int   g_srt_src[EN];                          // src node per sorted edge slot
__device__ int   g_cnt[N_NODES];
__device__ int   g_off[N_NODES + 1];
__device__ int   g_cur[N_NODES];
__device__ __align__(16) float g_out[N_NODES * HC];     // aggregated messages
__device__ __align__(16) float g_f1[N_NODES * DFF];     // FFN hidden

// ---------------- CSR build ----------------
__global__ void zero_cnt_kernel() {
    int i = blockIdx.x * blockDim.x + threadIdx.x;
    if (i < N_NODES) g_cnt[i] = 0;
}

__global__ void hist_kernel(const int* __restrict__ ei) {
    int i = blockIdx.x * blockDim.x + threadIdx.x;
    if (i >= EN) return;
    int d = (i < E_EDGES) ? ei[E_EDGES + i] : (i - E_EDGES);
    atomicAdd(&g_cnt[d], 1);
}

__global__ void scan_kernel() {
    __shared__ int s[1024];
    const int CH = (N_NODES + 1023) / 1024;   // 20
    int tid = threadIdx.x;
    int base_i = tid * CH;
    int loc[CH];
    int tot = 0;
#pragma unroll
    for (int i = 0; i < CH; i++) {
        int idx = base_i + i;
        int v = (idx < N_NODES) ? g_cnt[idx] : 0;
        loc[i] = tot;
        tot += v;
    }
    s[tid] = tot;
    __syncthreads();
    for (int o = 1; o < 1024; o <<= 1) {
        int v = (tid >= o) ? s[tid - o] : 0;
        __syncthreads();
        s[tid] += v;
        __syncthreads();
    }
    int base = s[tid] - tot;
#pragma unroll
    for (int i = 0; i < CH; i++) {
        int idx = base_i + i;
        if (idx < N_NODES) {
            int v = base + loc[i];
            g_off[idx] = v;
            g_cur[idx] = v;
        }
    }
    if (tid == 1023) g_off[N_NODES] = s[1023];
}

__global__ void scatter_kernel(const int* __restrict__ ei) {
    int i = blockIdx.x * blockDim.x + threadIdx.x;
    if (i >= EN) return;
    int s, d;
    if (i < E_EDGES) { s = ei[i]; d = ei[E_EDGES + i]; }
    else             { s = d = i - E_EDGES; }
    int pos = atomicAdd(&g_cur[d], 1);
    g_srt_src[pos] = s;
}

// ---------------- tf32 tensor-core GEMM ------------------------------------
// C[M,N] = A[M,K] @ B[K,N] (+bias, epilogue). tf32 inputs, fp32 accum.
// BM=128, BN=64, BK=16. 256 threads = 8 warps (4 m x 2 n), 32x32 warp tile.
// EPI: 0 = +bias (nullable), 1 = (+bias)*scale, 2 = gelu(+bias)

__device__ __forceinline__ uint32_t f2tf32(float f) {
    uint32_t u;
    asm("cvt.rna.tf32.f32 %0, %1;" : "=r"(u) : "f"(f));
    return u;
}

template <int EPI>
__global__ __launch_bounds__(256) void mma_gemm_kernel(
    const float* __restrict__ A, const float* __restrict__ B,
    const float* __restrict__ bias, float* __restrict__ C,
    int M, int N, int K, float scale)
{
    const int BM = 128, BN = 64, BK = 16;
    __shared__ __align__(16) uint32_t As[BM][BK + 4];   // [m][k], stride 20
    __shared__ __align__(16) uint32_t Bs[BK][BN + 8];   // [k][n], stride 72

    int tid = threadIdx.x;
    int lane = tid & 31;
    int w = tid >> 5;
    int wm = (w & 3) * 32;          // warp row offset within block tile
    int wn = (w >> 2) * 32;         // warp col offset
    int gID = lane >> 2;            // 0..7
    int tg  = lane & 3;             // 0..3
    int row0 = blockIdx.y * BM, col0 = blockIdx.x * BN;

    float acc[2][4][4];
#pragma unroll
    for (int mi = 0; mi < 2; mi++)
#pragma unroll
        for (int ni = 0; ni < 4; ni++)
#pragma unroll
            for (int r = 0; r < 4; r++) acc[mi][ni][r] = 0.f;

    for (int kk = 0; kk < K; kk += BK) {
        // load A tile: 128x16 = 512 float4, 2 per thread
#pragma unroll
        for (int t = 0; t < 2; t++) {
            int idx = tid + t * 256;
            int m = idx >> 2;
            int k4 = (idx & 3) * 4;
            int gm = row0 + m;
            float4 v = make_float4(0.f, 0.f, 0.f, 0.f);
            if (gm < M) v = *reinterpret_cast<const float4*>(&A[(long)gm * K + kk + k4]);
            uint4 u = make_uint4(f2tf32(v.x), f2tf32(v.y), f2tf32(v.z), f2tf32(v.w));
            *reinterpret_cast<uint4*>(&As[m][k4]) = u;
        }
        // load B tile: 16x64 = 256 float4, 1 per thread
        {
            int k = tid >> 4;
            int n4 = (tid & 15) * 4;
            float4 v = *reinterpret_cast<const float4*>(&B[(long)(kk + k) * N + col0 + n4]);
            Bs[k][n4 + 0] = f2tf32(v.x);
            Bs[k][n4 + 1] = f2tf32(v.y);
            Bs[k][n4 + 2] = f2tf32(v.z);
            Bs[k][n4 + 3] = f2tf32(v.w);
        }
        __syncthreads();

#pragma unroll
        for (int ks = 0; ks < 2; ks++) {
            int k0 = ks * 8;
            uint32_t a[2][4];
#pragma unroll
            for (int mi = 0; mi < 2; mi++) {
                int r = wm + mi * 16;
                a[mi][0] = As[r + gID][k0 + tg];
                a[mi][1] = As[r + gID + 8][k0 + tg];
                a[mi][2] = As[r + gID][k0 + tg + 4];
                a[mi][3] = As[r + gID + 8][k0 + tg + 4];
            }
#pragma unroll
            for (int ni = 0; ni < 4; ni++) {
                uint32_t b0 = Bs[k0 + tg][wn + ni * 8 + gID];
                uint32_t b1 = Bs[k0 + tg + 4][wn + ni * 8 + gID];
#pragma unroll
                for (int mi = 0; mi < 2; mi++) {
                    asm volatile(
                        "mma.sync.aligned.m16n8k8.row.col.f32.tf32.tf32.f32 "
                        "{%0,%1,%2,%3}, {%4,%5,%6,%7}, {%8,%9}, {%0,%1,%2,%3};\n"
                        : "+f"(acc[mi][ni][0]), "+f"(acc[mi][ni][1]),
                          "+f"(acc[mi][ni][2]), "+f"(acc[mi][ni][3])
                        : "r"(a[mi][0]), "r"(a[mi][1]), "r"(a[mi][2]), "r"(a[mi][3]),
                          "r"(b0), "r"(b1));
                }
            }
        }
        __syncthreads();
    }

    // epilogue
#pragma unroll
    for (int mi = 0; mi < 2; mi++) {
#pragma unroll
        for (int ni = 0; ni < 4; ni++) {
            int r = row0 + wm + mi * 16 + gID;
            int cb = col0 + wn + ni * 8 + tg * 2;
            float bv0 = 0.f, bv1 = 0.f;
            if (bias) { bv0 = bias[cb]; bv1 = bias[cb + 1]; }
#pragma unroll
            for (int half = 0; half < 2; half++) {
                int gr = r + half * 8;
                if (gr >= M) continue;
                float v0 = acc[mi][ni][half * 2 + 0] + bv0;
                float v1 = acc[mi][ni][half * 2 + 1] + bv1;
                if (EPI == 1) { v0 *= scale; v1 *= scale; }
                if (EPI == 2) {
                    v0 = 0.5f * v0 * (1.0f + erff(v0 * 0.70710678118654752f));
                    v1 = 0.5f * v1 * (1.0f + erff(v1 * 0.70710678118654752f));
                }
                *reinterpret_cast<float2*>(&C[(long)gr * N + cb]) = make_float2(v0, v1);
            }
        }
    }
}

// ---------------- attention scores: a_s/a_d per (node, head) ----------------
__global__ void att_kernel(const float* __restrict__ att_s,
                           const float* __restrict__ att_d)
{
    int gw = (blockIdx.x * blockDim.x + threadIdx.x) >> 5;
    if (gw >= N_NODES) return;
    int lane = threadIdx.x & 31;
    int hh = lane >> 3;
    int sub = lane & 7;
    const float* xr = g_xh + (long)gw * HC + hh * CD;
    const float* ws = att_s + hh * CD;
    const float* wd = att_d + hh * CD;
    float ss = 0.f, sd = 0.f;
#pragma unroll
    for (int j = 0; j < 8; j++) {
        float v = xr[sub + j * 8];
        ss = fmaf(v, ws[sub + j * 8], ss);
        sd = fmaf(v, wd[sub + j * 8], sd);
    }
#pragma unroll
    for (int o = 4; o > 0; o >>= 1) {
        ss += __shfl_down_sync(0xffffffffu, ss, o, 8);
        sd += __shfl_down_sync(0xffffffffu, sd, o, 8);
    }
    if (sub == 0) {
        g_as[gw * 4 + hh] = ss;
        g_ad[gw * 4 + hh] = sd;
    }
}

__device__ __forceinline__ float lrelu(float x) { return x > 0.f ? x : 0.2f * x; }

// ---------------- segment softmax over incoming edges (warp per dst) --------
__global__ void softmax_kernel()
{
    int d = (blockIdx.x * blockDim.x + threadIdx.x) >> 5;
    if (d >= N_NODES) return;
    int lane = threadIdx.x & 31;
    int beg = g_off[d], end = g_off[d + 1];
    float4 ad = *reinterpret_cast<const float4*>(g_ad + d * 4);

    float m0 = -INFINITY, m1 = -INFINITY, m2 = -INFINITY, m3 = -INFINITY;
    for (int p = beg + lane; p < end; p += 32) {
        int s = g_srt_src[p];
        float4 as = *reinterpret_cast<const float4*>(g_as + s * 4);
        m0 = fmaxf(m0, lrelu(as.x + ad.x));
        m1 = fmaxf(m1, lrelu(as.y + ad.y));
        m2 = fmaxf(m2, lrelu(as.z + ad.z));
        m3 = fmaxf(m3, lrelu(as.w + ad.w));
    }
#pragma unroll
    for (int o = 16; o > 0; o >>= 1) {
        m0 = fmaxf(m0, __shfl_xor_sync(0xffffffffu, m0, o));
        m1 = fmaxf(m1, __shfl_xor_sync(0xffffffffu, m1, o));
        m2 = fmaxf(m2, __shfl_xor_sync(0xffffffffu, m2, o));
        m3 = fmaxf(m3, __shfl_xor_sync(0xffffffffu, m3, o));
    }
    float z0 = 0.f, z1 = 0.f, z2 = 0.f, z3 = 0.f;
    for (int p = beg + lane; p < end; p += 32) {
        int s = g_srt_src[p];
        float4 as = *reinterpret_cast<const float4*>(g_as + s * 4);
        float4 ex;
        ex.x = expf(lrelu(as.x + ad.x) - m0);
        ex.y = expf(lrelu(as.y + ad.y) - m1);
        ex.z = expf(lrelu(as.z + ad.z) - m2);
        ex.w = expf(lrelu(as.w + ad.w) - m3);
        *reinterpret_cast<float4*>(g_alpha + (long)p * 4) = ex;
        z0 += ex.x; z1 += ex.y; z2 += ex.z; z3 += ex.w;
    }
#pragma unroll
    for (int o = 16; o > 0; o >>= 1) {
        z0 += __shfl_xor_sync(0xffffffffu, z0, o);
        z1 += __shfl_xor_sync(0xffffffffu, z1, o);
        z2 += __shfl_xor_sync(0xffffffffu, z2, o);
        z3 += __shfl_xor_sync(0xffffffffu, z3, o);
    }
    float r0 = 1.f / (z0 + 1e-16f), r1 = 1.f / (z1 + 1e-16f);
    float r2 = 1.f / (z2 + 1e-16f), r3 = 1.f / (z3 + 1e-16f);
    for (int p = beg + lane; p < end; p += 32) {
        float4 v = *reinterpret_cast<float4*>(g_alpha + (long)p * 4);
        v.x *= r0; v.y *= r1; v.z *= r2; v.w *= r3;
        *reinterpret_cast<float4*>(g_alpha + (long)p * 4) = v;
    }
}

// ---------------- message aggregation (block per dst, no atomics) -----------
__global__ __launch_bounds__(256) void agg_kernel(const float* __restrict__ bc)
{
    int d = blockIdx.x;
    int c = threadIdx.x;           // output channel 0..255
    int hh = c >> 6;
    __shared__ int   s_src[64];
    __shared__ float s_al[64 * 4];
    int beg = g_off[d], end = g_off[d + 1];
    float acc = bc[c];
    for (int base = beg; base < end; base += 64) {
        int nn = min(64, end - base);
        if (c < nn) s_src[c] = g_srt_src[base + c];
        if (c < nn * 4) s_al[c] = g_alpha[(long)base * 4 + c];
        __syncthreads();
#pragma unroll 4
        for (int i = 0; i < nn; i++) {
            acc = fmaf(s_al[i * 4 + hh], g_xh[(long)s_src[i] * HC + c], acc);
        }
        __syncthreads();
    }
    g_out[(long)d * HC + c] = acc;
}

// ---------------- layernorm + residual (warp per node) ----------------------
__global__ void ln_kernel(const float* __restrict__ f,
                          const float* __restrict__ gam,
                          const float* __restrict__ bet,
                          float* __restrict__ h)
{
    int node = (blockIdx.x * blockDim.x + threadIdx.x) >> 5;
    if (node >= N_NODES) return;
    int lane = threadIdx.x & 31;
    float v0 = f[(long)node * HID + lane];
    float v1 = f[(long)node * HID + 32 + lane];
    float s = v0 + v1;
#pragma unroll
    for (int o = 16; o > 0; o >>= 1) s += __shfl_xor_sync(0xffffffffu, s, o);
    float mean = s * (1.f / 64.f);
    float d0 = v0 - mean, d1 = v1 - mean;
    float vv = d0 * d0 + d1 * d1;
#pragma unroll
    for (int o = 16; o > 0; o >>= 1) vv += __shfl_xor_sync(0xffffffffu, vv, o);
    float rstd = rsqrtf(vv * (1.f / 64.f) + 1e-5f);
    h[(long)node * HID + lane]      += d0 * rstd * gam[lane]      + bet[lane];
    h[(long)node * HID + 32 + lane] += d1 * rstd * gam[32 + lane] + bet[32 + lane];
}

// ---------------- driver -----------------------------------------------------
extern "C" void kernel_launch(void* const* d_in, const int* in_sizes, int n_in,
                              void* d_out, int out_size)
{
    const float* x     = (const float*)d_in[0];
    const int*   ei    = (const int*)  d_in[1];
    const float* We    = (const float*)d_in[2];
    const float* be    = (const float*)d_in[3];
    const float* Wc    = (const float*)d_in[4];
    const float* att_s = (const float*)d_in[5];
    const float* att_d = (const float*)d_in[6];
    const float* bc    = (const float*)d_in[7];
    const float* W1    = (const float*)d_in[8];
    const float* b1    = (const float*)d_in[9];
    const float* W2    = (const float*)d_in[10];
    const float* b2    = (const float*)d_in[11];
    const float* lng   = (const float*)d_in[12];
    const float* lnb   = (const float*)d_in[13];
    float* h = (float*)d_out;

    float *p_xh, *p_out, *p_f1;
    cudaGetSymbolAddress((void**)&p_xh,  g_xh);
    cudaGetSymbolAddress((void**)&p_out, g_out);
    cudaGetSymbolAddress((void**)&p_f1,  g_f1);

    // ---- CSR build (once; reused across layers) ----
    zero_cnt_kernel<<<(N_NODES + 255) / 256, 256>>>();
    hist_kernel<<<(EN + 255) / 256, 256>>>(ei);
    scan_kernel<<<1, 1024>>>();
    scatter_kernel<<<(EN + 255) / 256, 256>>>(ei);

    const int GY = (N_NODES + 127) / 128;

    // ---- embed: h = (x @ We + be) * 8 ----
    mma_gemm_kernel<1><<<dim3(HID / 64, GY), 256>>>(x, We, be, h,
                                                    N_NODES, HID, IN_DIM, 8.0f);

    for (int l = 0; l < NL; l++) {
        // xh = h @ Wc[l]
        mma_gemm_kernel<0><<<dim3(HC / 64, GY), 256>>>(h, Wc + (long)l * HID * HC,
                                                       nullptr, p_xh,
                                                       N_NODES, HC, HID, 0.f);
        att_kernel<<<(N_NODES * 32 + 255) / 256, 256>>>(att_s + l * NH * CD,
                                                        att_d + l * NH * CD);
        softmax_kernel<<<(N_NODES * 32 + 255) / 256, 256>>>();
        agg_kernel<<<N_NODES, 256>>>(bc + l * HC);
        // f1 = gelu(out @ W1[l] + b1[l])
        mma_gemm_kernel<2><<<dim3(DFF / 64, GY), 256>>>(p_out, W1 + (long)l * HC * DFF,
                                                        b1 + l * DFF, p_f1,
                                                        N_NODES, DFF, HC, 0.f);
        // f2 = f1 @ W2[l] + b2[l]  (reuse g_xh as f2 buffer)
        mma_gemm_kernel<0><<<dim3(HID / 64, GY), 256>>>(p_f1, W2 + (long)l * DFF * HID,
                                                        b2 + l * HID, p_xh,
                                                        N_NODES, HID, DFF, 0.f);
        // h += layernorm(f2)
        ln_kernel<<<(N_NODES * 32 + 255) / 256, 256>>>(p_xh, lng + l * HID,
                                                       lnb + l * HID, h);
    }
    (void)in_sizes; (void)n_in; (void)out_size;
}

// round 6
// speedup vs baseline: 1.6465x; 1.1433x over previous
#include <cuda_runtime.h>
#include <math.h>
#include <stdint.h>

#define N_NODES 20000
#define E_EDGES 320000
#define EN      340000   // E + N self loops
#define IN_DIM  256
#define HID     64
#define NH      4
#define CD      64
#define HC      256      // NH*CD
#define DFF     128
#define NL      4

// ---------------- scratch (module-global device memory; no runtime alloc) ----
__device__ __align__(16) float g_xh[N_NODES * HC];      // f2 buffer / aggregated-h buffer
__device__ __align__(16) float g_as[N_NODES * NH];      // attention src scores
__device__ __align__(16) float g_ad[N_NODES * NH];      // attention dst scores
__device__ __align__(16) float g_rz[N_NODES * NH];      // 1/(z+eps) per dst,head
__device__ __align__(16) float g_alpha[EN * NH];        // per-edge unnormalized exp weights
__device__ __align__(16) float g_watt[HID * 8];         // ws_hat[k][0..3], wd_hat[k][4..7]
__device__ int   g_srt_src[EN];
__device__ int   g_cnt[N_NODES];
__device__ int   g_off[N_NODES + 1];
__device__ int   g_cur[N_NODES];
__device__ __align__(16) float g_out[N_NODES * HC];     // projected messages
__device__ __align__(16) float g_f1[N_NODES * DFF];     // FFN hidden

// ---------------- CSR build ----------------
__global__ void zero_cnt_kernel() {
    int i = blockIdx.x * blockDim.x + threadIdx.x;
    if (i < N_NODES) g_cnt[i] = 0;
}

__global__ void hist_kernel(const int* __restrict__ ei) {
    int i = blockIdx.x * blockDim.x + threadIdx.x;
    if (i >= EN) return;
    int d = (i < E_EDGES) ? ei[E_EDGES + i] : (i - E_EDGES);
    atomicAdd(&g_cnt[d], 1);
}

__global__ void scan_kernel() {
    __shared__ int s[1024];
    const int CH = (N_NODES + 1023) / 1024;   // 20
    int tid = threadIdx.x;
    int base_i = tid * CH;
    int loc[CH];
    int tot = 0;
#pragma unroll
    for (int i = 0; i < CH; i++) {
        int idx = base_i + i;
        int v = (idx < N_NODES) ? g_cnt[idx] : 0;
        loc[i] = tot;
        tot += v;
    }
    s[tid] = tot;
    __syncthreads();
    for (int o = 1; o < 1024; o <<= 1) {
        int v = (tid >= o) ? s[tid - o] : 0;
        __syncthreads();
        s[tid] += v;
        __syncthreads();
    }
    int base = s[tid] - tot;
#pragma unroll
    for (int i = 0; i < CH; i++) {
        int idx = base_i + i;
        if (idx < N_NODES) {
            int v = base + loc[i];
            g_off[idx] = v;
            g_cur[idx] = v;
        }
    }
    if (tid == 1023) g_off[N_NODES] = s[1023];
}

__global__ void scatter_kernel(const int* __restrict__ ei) {
    int i = blockIdx.x * blockDim.x + threadIdx.x;
    if (i >= EN) return;
    int s, d;
    if (i < E_EDGES) { s = ei[i]; d = ei[E_EDGES + i]; }
    else             { s = d = i - E_EDGES; }
    int pos = atomicAdd(&g_cur[d], 1);
    g_srt_src[pos] = s;
}

// ---------------- tf32 tensor-core GEMM ------------------------------------
// C[M,N](ldc) = A[M,K](lda, + koff*blockIdx.x) @ B[K,N](ldb) + bias, epilogue.
// BM=128, BN=64, BK=16. 256 threads = 8 warps (4 m x 2 n), 32x32 warp tile.
// EPI: 0 = +bias (nullable), 1 = (+bias)*scale, 2 = gelu(+bias)

__device__ __forceinline__ uint32_t f2tf32(float f) {
    uint32_t u;
    asm("cvt.rna.tf32.f32 %0, %1;" : "=r"(u) : "f"(f));
    return u;
}

template <int EPI>
__global__ __launch_bounds__(256) void mma_gemm_kernel(
    const float* __restrict__ A, const float* __restrict__ B,
    const float* __restrict__ bias, float* __restrict__ C,
    int M, int N, int K, int lda, int ldb, int ldc, int koff, float scale)
{
    const int BM = 128, BN = 64, BK = 16;
    __shared__ __align__(16) uint32_t As[BM][BK + 4];   // [m][k], stride 20
    __shared__ __align__(16) uint32_t Bs[BK][BN + 8];   // [k][n], stride 72

    int tid = threadIdx.x;
    int lane = tid & 31;
    int w = tid >> 5;
    int wm = (w & 3) * 32;
    int wn = (w >> 2) * 32;
    int gID = lane >> 2;
    int tg  = lane & 3;
    int row0 = blockIdx.y * BM, col0 = blockIdx.x * BN;
    int akoff = koff * blockIdx.x;

    float acc[2][4][4];
#pragma unroll
    for (int mi = 0; mi < 2; mi++)
#pragma unroll
        for (int ni = 0; ni < 4; ni++)
#pragma unroll
            for (int r = 0; r < 4; r++) acc[mi][ni][r] = 0.f;

    for (int kk = 0; kk < K; kk += BK) {
#pragma unroll
        for (int t = 0; t < 2; t++) {
            int idx = tid + t * 256;
            int m = idx >> 2;
            int k4 = (idx & 3) * 4;
            int gm = row0 + m;
            float4 v = make_float4(0.f, 0.f, 0.f, 0.f);
            if (gm < M) v = *reinterpret_cast<const float4*>(&A[(long)gm * lda + akoff + kk + k4]);
            uint4 u = make_uint4(f2tf32(v.x), f2tf32(v.y), f2tf32(v.z), f2tf32(v.w));
            *reinterpret_cast<uint4*>(&As[m][k4]) = u;
        }
        {
            int k = tid >> 4;
            int n4 = (tid & 15) * 4;
            float4 v = *reinterpret_cast<const float4*>(&B[(long)(kk + k) * ldb + col0 + n4]);
            Bs[k][n4 + 0] = f2tf32(v.x);
            Bs[k][n4 + 1] = f2tf32(v.y);
            Bs[k][n4 + 2] = f2tf32(v.z);
            Bs[k][n4 + 3] = f2tf32(v.w);
        }
        __syncthreads();

#pragma unroll
        for (int ks = 0; ks < 2; ks++) {
            int k0 = ks * 8;
            uint32_t a[2][4];
#pragma unroll
            for (int mi = 0; mi < 2; mi++) {
                int r = wm + mi * 16;
                a[mi][0] = As[r + gID][k0 + tg];
                a[mi][1] = As[r + gID + 8][k0 + tg];
                a[mi][2] = As[r + gID][k0 + tg + 4];
                a[mi][3] = As[r + gID + 8][k0 + tg + 4];
            }
#pragma unroll
            for (int ni = 0; ni < 4; ni++) {
                uint32_t b0 = Bs[k0 + tg][wn + ni * 8 + gID];
                uint32_t b1 = Bs[k0 + tg + 4][wn + ni * 8 + gID];
#pragma unroll
                for (int mi = 0; mi < 2; mi++) {
                    asm volatile(
                        "mma.sync.aligned.m16n8k8.row.col.f32.tf32.tf32.f32 "
                        "{%0,%1,%2,%3}, {%4,%5,%6,%7}, {%8,%9}, {%0,%1,%2,%3};\n"
                        : "+f"(acc[mi][ni][0]), "+f"(acc[mi][ni][1]),
                          "+f"(acc[mi][ni][2]), "+f"(acc[mi][ni][3])
                        : "r"(a[mi][0]), "r"(a[mi][1]), "r"(a[mi][2]), "r"(a[mi][3]),
                          "r"(b0), "r"(b1));
                }
            }
        }
        __syncthreads();
    }

#pragma unroll
    for (int mi = 0; mi < 2; mi++) {
#pragma unroll
        for (int ni = 0; ni < 4; ni++) {
            int r = row0 + wm + mi * 16 + gID;
            int cb = col0 + wn + ni * 8 + tg * 2;
            float bv0 = 0.f, bv1 = 0.f;
            if (bias) { bv0 = bias[cb]; bv1 = bias[cb + 1]; }
#pragma unroll
            for (int half = 0; half < 2; half++) {
                int gr = r + half * 8;
                if (gr >= M) continue;
                float v0 = acc[mi][ni][half * 2 + 0] + bv0;
                float v1 = acc[mi][ni][half * 2 + 1] + bv1;
                if (EPI == 1) { v0 *= scale; v1 *= scale; }
                if (EPI == 2) {
                    v0 = 0.5f * v0 * (1.0f + erff(v0 * 0.70710678118654752f));
                    v1 = 0.5f * v1 * (1.0f + erff(v1 * 0.70710678118654752f));
                }
                *reinterpret_cast<float2*>(&C[(long)gr * ldc + cb]) = make_float2(v0, v1);
            }
        }
    }
}

// ---------------- folded attention weights: ws_hat = Wc @ att ---------------
// block 0: src, block 1: dst. 256 threads: k = tid>>2 (0..63), j = tid&3 (head)
__global__ void watt_prep_kernel(const float* __restrict__ Wc_l,
                                 const float* __restrict__ att_s_l,
                                 const float* __restrict__ att_d_l)
{
    int tid = threadIdx.x;
    int k = tid >> 2, j = tid & 3;
    const float* att = (blockIdx.x == 0) ? att_s_l : att_d_l;
    const float* wr = Wc_l + (long)k * HC + j * CD;
    const float* ar = att + j * CD;
    float s = 0.f;
#pragma unroll 8
    for (int c = 0; c < CD; c++) s = fmaf(wr[c], ar[c], s);
    g_watt[k * 8 + blockIdx.x * 4 + j] = s;
}

// ---------------- scores from h: a_s[n,h] = h[n] . ws_hat[:,h] --------------
__global__ void scores_kernel(const float* __restrict__ h)
{
    int n = (blockIdx.x * blockDim.x + threadIdx.x) >> 5;
    if (n >= N_NODES) return;
    int lane = threadIdx.x & 31;
    float2 hv = *reinterpret_cast<const float2*>(&h[(long)n * HID + lane * 2]);
    int k0 = lane * 2;
    float4 s0 = *reinterpret_cast<const float4*>(&g_watt[k0 * 8]);
    float4 d0 = *reinterpret_cast<const float4*>(&g_watt[k0 * 8 + 4]);
    float4 s1 = *reinterpret_cast<const float4*>(&g_watt[k0 * 8 + 8]);
    float4 d1 = *reinterpret_cast<const float4*>(&g_watt[k0 * 8 + 12]);
    float v[8];
    v[0] = hv.x * s0.x + hv.y * s1.x;
    v[1] = hv.x * s0.y + hv.y * s1.y;
    v[2] = hv.x * s0.z + hv.y * s1.z;
    v[3] = hv.x * s0.w + hv.y * s1.w;
    v[4] = hv.x * d0.x + hv.y * d1.x;
    v[5] = hv.x * d0.y + hv.y * d1.y;
    v[6] = hv.x * d0.z + hv.y * d1.z;
    v[7] = hv.x * d0.w + hv.y * d1.w;
#pragma unroll
    for (int j = 0; j < 8; j++)
#pragma unroll
        for (int o = 16; o > 0; o >>= 1)
            v[j] += __shfl_xor_sync(0xffffffffu, v[j], o);
    if (lane == 0) {
        *reinterpret_cast<float4*>(&g_as[n * 4]) = make_float4(v[0], v[1], v[2], v[3]);
        *reinterpret_cast<float4*>(&g_ad[n * 4]) = make_float4(v[4], v[5], v[6], v[7]);
    }
}

__device__ __forceinline__ float lrelu(float x) { return x > 0.f ? x : 0.2f * x; }

// ---------------- segment softmax (2 passes; 1/z folded into agg) ----------
__global__ void softmax_kernel()
{
    int d = (blockIdx.x * blockDim.x + threadIdx.x) >> 5;
    if (d >= N_NODES) return;
    int lane = threadIdx.x & 31;
    int beg = g_off[d], end = g_off[d + 1];
    float4 ad = *reinterpret_cast<const float4*>(g_ad + d * 4);

    float m0 = -INFINITY, m1 = -INFINITY, m2 = -INFINITY, m3 = -INFINITY;
    for (int p = beg + lane; p < end; p += 32) {
        int s = g_srt_src[p];
        float4 as = *reinterpret_cast<const float4*>(g_as + s * 4);
        m0 = fmaxf(m0, lrelu(as.x + ad.x));
        m1 = fmaxf(m1, lrelu(as.y + ad.y));
        m2 = fmaxf(m2, lrelu(as.z + ad.z));
        m3 = fmaxf(m3, lrelu(as.w + ad.w));
    }
#pragma unroll
    for (int o = 16; o > 0; o >>= 1) {
        m0 = fmaxf(m0, __shfl_xor_sync(0xffffffffu, m0, o));
        m1 = fmaxf(m1, __shfl_xor_sync(0xffffffffu, m1, o));
        m2 = fmaxf(m2, __shfl_xor_sync(0xffffffffu, m2, o));
        m3 = fmaxf(m3, __shfl_xor_sync(0xffffffffu, m3, o));
    }
    float z0 = 0.f, z1 = 0.f, z2 = 0.f, z3 = 0.f;
    for (int p = beg + lane; p < end; p += 32) {
        int s = g_srt_src[p];
        float4 as = *reinterpret_cast<const float4*>(g_as + s * 4);
        float4 ex;
        ex.x = expf(lrelu(as.x + ad.x) - m0);
        ex.y = expf(lrelu(as.y + ad.y) - m1);
        ex.z = expf(lrelu(as.z + ad.z) - m2);
        ex.w = expf(lrelu(as.w + ad.w) - m3);
        *reinterpret_cast<float4*>(g_alpha + (long)p * 4) = ex;
        z0 += ex.x; z1 += ex.y; z2 += ex.z; z3 += ex.w;
    }
#pragma unroll
    for (int o = 16; o > 0; o >>= 1) {
        z0 += __shfl_xor_sync(0xffffffffu, z0, o);
        z1 += __shfl_xor_sync(0xffffffffu, z1, o);
        z2 += __shfl_xor_sync(0xffffffffu, z2, o);
        z3 += __shfl_xor_sync(0xffffffffu, z3, o);
    }
    if (lane == 0) {
        *reinterpret_cast<float4*>(&g_rz[d * 4]) =
            make_float4(1.f / (z0 + 1e-16f), 1.f / (z1 + 1e-16f),
                        1.f / (z2 + 1e-16f), 1.f / (z3 + 1e-16f));
    }
}

// ---------------- aggregation of h (warp per dst): ah[d,h,:]=Σ α·h[src] ----
__global__ __launch_bounds__(256) void agg_h_kernel(const float* __restrict__ h,
                                                    float* __restrict__ ah)
{
    int d = (blockIdx.x * blockDim.x + threadIdx.x) >> 5;
    if (d >= N_NODES) return;
    int lane = threadIdx.x & 31;
    int beg = g_off[d], end = g_off[d + 1];

    float2 a0 = make_float2(0.f, 0.f), a1 = a0, a2 = a0, a3 = a0;
    int p = beg;
    for (; p + 1 < end; p += 2) {
        int s0 = g_srt_src[p];
        int s1 = g_srt_src[p + 1];
        float4 al0 = *reinterpret_cast<const float4*>(&g_alpha[(long)p * 4]);
        float4 al1 = *reinterpret_cast<const float4*>(&g_alpha[(long)(p + 1) * 4]);
        float2 h0 = *reinterpret_cast<const float2*>(&h[(long)s0 * HID + lane * 2]);
        float2 h1 = *reinterpret_cast<const float2*>(&h[(long)s1 * HID + lane * 2]);
        a0.x = fmaf(al0.x, h0.x, a0.x); a0.y = fmaf(al0.x, h0.y, a0.y);
        a1.x = fmaf(al0.y, h0.x, a1.x); a1.y = fmaf(al0.y, h0.y, a1.y);
        a2.x = fmaf(al0.z, h0.x, a2.x); a2.y = fmaf(al0.z, h0.y, a2.y);
        a3.x = fmaf(al0.w, h0.x, a3.x); a3.y = fmaf(al0.w, h0.y, a3.y);
        a0.x = fmaf(al1.x, h1.x, a0.x); a0.y = fmaf(al1.x, h1.y, a0.y);
        a1.x = fmaf(al1.y, h1.x, a1.x); a1.y = fmaf(al1.y, h1.y, a1.y);
        a2.x = fmaf(al1.z, h1.x, a2.x); a2.y = fmaf(al1.z, h1.y, a2.y);
        a3.x = fmaf(al1.w, h1.x, a3.x); a3.y = fmaf(al1.w, h1.y, a3.y);
    }
    if (p < end) {
        int s0 = g_srt_src[p];
        float4 al0 = *reinterpret_cast<const float4*>(&g_alpha[(long)p * 4]);
        float2 h0 = *reinterpret_cast<const float2*>(&h[(long)s0 * HID + lane * 2]);
        a0.x = fmaf(al0.x, h0.x, a0.x); a0.y = fmaf(al0.x, h0.y, a0.y);
        a1.x = fmaf(al0.y, h0.x, a1.x); a1.y = fmaf(al0.y, h0.y, a1.y);
        a2.x = fmaf(al0.z, h0.x, a2.x); a2.y = fmaf(al0.z, h0.y, a2.y);
        a3.x = fmaf(al0.w, h0.x, a3.x); a3.y = fmaf(al0.w, h0.y, a3.y);
    }
    float4 rz = *reinterpret_cast<const float4*>(&g_rz[d * 4]);
    a0.x *= rz.x; a0.y *= rz.x;
    a1.x *= rz.y; a1.y *= rz.y;
    a2.x *= rz.z; a2.y *= rz.z;
    a3.x *= rz.w; a3.y *= rz.w;
    long base = (long)d * HC + lane * 2;
    *reinterpret_cast<float2*>(&ah[base + 0 * CD]) = a0;
    *reinterpret_cast<float2*>(&ah[base + 1 * CD]) = a1;
    *reinterpret_cast<float2*>(&ah[base + 2 * CD]) = a2;
    *reinterpret_cast<float2*>(&ah[base + 3 * CD]) = a3;
}

// ---------------- layernorm + residual (warp per node) ----------------------
__global__ void ln_kernel(const float* __restrict__ f,
                          const float* __restrict__ gam,
                          const float* __restrict__ bet,
                          float* __restrict__ h)
{
    int node = (blockIdx.x * blockDim.x + threadIdx.x) >> 5;
    if (node >= N_NODES) return;
    int lane = threadIdx.x & 31;
    float v0 = f[(long)node * HID + lane];
    float v1 = f[(long)node * HID + 32 + lane];
    float s = v0 + v1;
#pragma unroll
    for (int o = 16; o > 0; o >>= 1) s += __shfl_xor_sync(0xffffffffu, s, o);
    float mean = s * (1.f / 64.f);
    float d0 = v0 - mean, d1 = v1 - mean;
    float vv = d0 * d0 + d1 * d1;
#pragma unroll
    for (int o = 16; o > 0; o >>= 1) vv += __shfl_xor_sync(0xffffffffu, vv, o);
    float rstd = rsqrtf(vv * (1.f / 64.f) + 1e-5f);
    h[(long)node * HID + lane]      += d0 * rstd * gam[lane]      + bet[lane];
    h[(long)node * HID + 32 + lane] += d1 * rstd * gam[32 + lane] + bet[32 + lane];
}

// ---------------- driver -----------------------------------------------------
extern "C" void kernel_launch(void* const* d_in, const int* in_sizes, int n_in,
                              void* d_out, int out_size)
{
    const float* x     = (const float*)d_in[0];
    const int*   ei    = (const int*)  d_in[1];
    const float* We    = (const float*)d_in[2];
    const float* be    = (const float*)d_in[3];
    const float* Wc    = (const float*)d_in[4];
    const float* att_s = (const float*)d_in[5];
    const float* att_d = (const float*)d_in[6];
    const float* bc    = (const float*)d_in[7];
    const float* W1    = (const float*)d_in[8];
    const float* b1    = (const float*)d_in[9];
    const float* W2    = (const float*)d_in[10];
    const float* b2    = (const float*)d_in[11];
    const float* lng   = (const float*)d_in[12];
    const float* lnb   = (const float*)d_in[13];
    float* h = (float*)d_out;

    float *p_xh, *p_out, *p_f1;
    cudaGetSymbolAddress((void**)&p_xh,  g_xh);
    cudaGetSymbolAddress((void**)&p_out, g_out);
    cudaGetSymbolAddress((void**)&p_f1,  g_f1);

    // ---- CSR build (once; reused across layers) ----
    zero_cnt_kernel<<<(N_NODES + 255) / 256, 256>>>();
    hist_kernel<<<(EN + 255) / 256, 256>>>(ei);
    scan_kernel<<<1, 1024>>>();
    scatter_kernel<<<(EN + 255) / 256, 256>>>(ei);

    const int GY = (N_NODES + 127) / 128;
    const int WG = (N_NODES * 32 + 255) / 256;   // warp-per-node grids

    // ---- embed: h = (x @ We + be) * 8 ----
    mma_gemm_kernel<1><<<dim3(1, GY), 256>>>(x, We, be, h,
                                             N_NODES, HID, IN_DIM,
                                             IN_DIM, HID, HID, 0, 8.0f);

    for (int l = 0; l < NL; l++) {
        const float* Wc_l = Wc + (long)l * HID * HC;
        // folded attention weight vectors
        watt_prep_kernel<<<2, 256>>>(Wc_l, att_s + l * NH * CD, att_d + l * NH * CD);
        // scores from h
        scores_kernel<<<WG, 256>>>(h);
        // edge softmax (unnormalized alpha + 1/z)
        softmax_kernel<<<WG, 256>>>();
        // aggregate h per head  -> g_xh used as ah buffer
        agg_h_kernel<<<WG, 256>>>(h, p_xh);
        // project: out[:, head*64:+64] = ah[:, head*64:+64] @ Wc_l[:, head*64:+64] + bc
        mma_gemm_kernel<0><<<dim3(NH, GY), 256>>>(p_xh, Wc_l, bc + l * HC, p_out,
                                                  N_NODES, CD, HID,
                                                  HC, HC, HC, CD, 0.f);
        // f1 = gelu(out @ W1[l] + b1[l])
        mma_gemm_kernel<2><<<dim3(DFF / 64, GY), 256>>>(p_out, W1 + (long)l * HC * DFF,
                                                        b1 + l * DFF, p_f1,
                                                        N_NODES, DFF, HC,
                                                        HC, DFF, DFF, 0, 0.f);
        // f2 = f1 @ W2[l] + b2[l]  (reuse g_xh as f2 buffer)
        mma_gemm_kernel<0><<<dim3(1, GY), 256>>>(p_f1, W2 + (long)l * DFF * HID,
                                                 b2 + l * HID, p_xh,
                                                 N_NODES, HID, DFF,
                                                 DFF, HID, HID, 0, 0.f);
        // h += layernorm(f2)
        ln_kernel<<<WG, 256>>>(p_xh, lng + l * HID, lnb + l * HID, h);
    }
    (void)in_sizes; (void)n_in; (void)out_size;
}

// round 7
// speedup vs baseline: 1.8844x; 1.1445x over previous
#include <cuda_runtime.h>
#include <math.h>
#include <stdint.h>

#define N_NODES 20000
#define E_EDGES 320000
#define EN      340000   // E + N self loops
#define IN_DIM  256
#define HID     64
#define NH      4
#define CD      64
#define HC      256      // NH*CD
#define DFF     128
#define NL      4

// ---------------- scratch (module-global device memory; no runtime alloc) ----
__device__ __align__(16) float g_xh[N_NODES * HC];      // f2 buffer / aggregated-h buffer
__device__ __align__(16) float g_as[N_NODES * NH];      // attention src scores
__device__ __align__(16) float g_ad[N_NODES * NH];      // attention dst scores
__device__ __align__(16) float g_rz[N_NODES * NH];      // 1/(z+eps) per dst,head
__device__ __align__(16) float g_alpha[EN * NH];        // per-edge unnormalized exp weights
__device__ __align__(16) float g_watt[NL * HID * 8];    // per-layer ws_hat/wd_hat
__device__ int   g_srt_src[EN];
__device__ int   g_cnt[N_NODES];
__device__ int   g_off[N_NODES + 1];
__device__ int   g_cur[N_NODES];
__device__ __align__(16) float g_out[N_NODES * HC];     // projected messages
__device__ __align__(16) float g_f1[N_NODES * DFF];     // FFN hidden

// ---------------- CSR build ----------------
__global__ void zero_cnt_kernel() {
    int i = blockIdx.x * blockDim.x + threadIdx.x;
    if (i < N_NODES) g_cnt[i] = 0;
}

__global__ void hist_kernel(const int* __restrict__ ei) {
    int i = blockIdx.x * blockDim.x + threadIdx.x;
    if (i >= EN) return;
    int d = (i < E_EDGES) ? ei[E_EDGES + i] : (i - E_EDGES);
    atomicAdd(&g_cnt[d], 1);
}

__global__ void scan_kernel() {
    __shared__ int s[1024];
    const int CH = (N_NODES + 1023) / 1024;   // 20
    int tid = threadIdx.x;
    int base_i = tid * CH;
    int loc[CH];
    int tot = 0;
#pragma unroll
    for (int i = 0; i < CH; i++) {
        int idx = base_i + i;
        int v = (idx < N_NODES) ? g_cnt[idx] : 0;
        loc[i] = tot;
        tot += v;
    }
    s[tid] = tot;
    __syncthreads();
    for (int o = 1; o < 1024; o <<= 1) {
        int v = (tid >= o) ? s[tid - o] : 0;
        __syncthreads();
        s[tid] += v;
        __syncthreads();
    }
    int base = s[tid] - tot;
#pragma unroll
    for (int i = 0; i < CH; i++) {
        int idx = base_i + i;
        if (idx < N_NODES) {
            int v = base + loc[i];
            g_off[idx] = v;
            g_cur[idx] = v;
        }
    }
    if (tid == 1023) g_off[N_NODES] = s[1023];
}

__global__ void scatter_kernel(const int* __restrict__ ei) {
    int i = blockIdx.x * blockDim.x + threadIdx.x;
    if (i >= EN) return;
    int s, d;
    if (i < E_EDGES) { s = ei[i]; d = ei[E_EDGES + i]; }
    else             { s = d = i - E_EDGES; }
    int pos = atomicAdd(&g_cur[d], 1);
    g_srt_src[pos] = s;
}

// ---------------- tf32 tensor-core GEMM, cp.async 2-stage -------------------
// C[M,N](ldc) = A[M,K](lda, + koff*blockIdx.x) @ B[K,N](ldb) + bias, epilogue.
// BM=128, BN=64, BK=16. 256 threads = 8 warps (4 m x 2 n), 32x32 warp tile.
// EPI: 0 = +bias (nullable), 1 = (+bias)*scale, 2 = gelu(+bias)

__device__ __forceinline__ uint32_t f2tf32(float f) {
    uint32_t u;
    asm("cvt.rna.tf32.f32 %0, %1;" : "=r"(u) : "f"(f));
    return u;
}

template <int EPI>
__global__ __launch_bounds__(256) void mma_gemm_kernel(
    const float* __restrict__ A, const float* __restrict__ B,
    const float* __restrict__ bias, float* __restrict__ C,
    int M, int N, int K, int lda, int ldb, int ldc, int koff, float scale)
{
    const int BM = 128, BN = 64, BK = 16;
    __shared__ __align__(16) float As[2][BM][BK + 4];   // row stride 20 floats = 80B (16B-mult)
    __shared__ __align__(16) float Bs[2][BK][BN + 8];   // row stride 72 floats = 288B

    int tid = threadIdx.x;
    int lane = tid & 31;
    int w = tid >> 5;
    int wm = (w & 3) * 32;
    int wn = (w >> 2) * 32;
    int gID = lane >> 2;
    int tg  = lane & 3;
    int row0 = blockIdx.y * BM, col0 = blockIdx.x * BN;
    int akoff = koff * blockIdx.x;

    int am  = tid >> 2;          // 0..63 (A rows, +64 for second chunk)
    int ak4 = (tid & 3) * 4;     // k offset
    int bk  = tid >> 4;          // 0..15
    int bn4 = (tid & 15) * 4;    // n offset

    float acc[2][4][4];
#pragma unroll
    for (int mi = 0; mi < 2; mi++)
#pragma unroll
        for (int ni = 0; ni < 4; ni++)
#pragma unroll
            for (int r = 0; r < 4; r++) acc[mi][ni][r] = 0.f;

    const int niter = K / BK;

#define ISSUE_TILE(IT, BUF)                                                     \
    {                                                                           \
        int kk_ = (IT) * BK;                                                    \
        _Pragma("unroll")                                                       \
        for (int t = 0; t < 2; t++) {                                           \
            int m_ = am + t * 64;                                               \
            int gm_ = row0 + m_;                                                \
            const float* src_ = &A[(long)gm_ * lda + akoff + kk_ + ak4];        \
            uint32_t dst_ = (uint32_t)__cvta_generic_to_shared(&As[BUF][m_][ak4]); \
            int sz_ = (gm_ < M) ? 16 : 0;                                       \
            asm volatile("cp.async.cg.shared.global [%0], [%1], 16, %2;\n"      \
                         :: "r"(dst_), "l"(src_), "r"(sz_));                    \
        }                                                                       \
        {                                                                       \
            const float* src_ = &B[(long)(kk_ + bk) * ldb + col0 + bn4];        \
            uint32_t dst_ = (uint32_t)__cvta_generic_to_shared(&Bs[BUF][bk][bn4]); \
            asm volatile("cp.async.cg.shared.global [%0], [%1], 16, 16;\n"      \
                         :: "r"(dst_), "l"(src_));                              \
        }                                                                       \
        asm volatile("cp.async.commit_group;\n");                               \
    }

    ISSUE_TILE(0, 0);

    for (int it = 0; it < niter; it++) {
        int buf = it & 1;
        asm volatile("cp.async.wait_group 0;\n");
        __syncthreads();
        if (it + 1 < niter) ISSUE_TILE(it + 1, (it + 1) & 1);

#pragma unroll
        for (int ks = 0; ks < 2; ks++) {
            int k0 = ks * 8;
            uint32_t a[2][4];
#pragma unroll
            for (int mi = 0; mi < 2; mi++) {
                int r = wm + mi * 16;
                a[mi][0] = f2tf32(As[buf][r + gID][k0 + tg]);
                a[mi][1] = f2tf32(As[buf][r + gID + 8][k0 + tg]);
                a[mi][2] = f2tf32(As[buf][r + gID][k0 + tg + 4]);
                a[mi][3] = f2tf32(As[buf][r + gID + 8][k0 + tg + 4]);
            }
#pragma unroll
            for (int ni = 0; ni < 4; ni++) {
                uint32_t b0 = f2tf32(Bs[buf][k0 + tg][wn + ni * 8 + gID]);
                uint32_t b1 = f2tf32(Bs[buf][k0 + tg + 4][wn + ni * 8 + gID]);
#pragma unroll
                for (int mi = 0; mi < 2; mi++) {
                    asm volatile(
                        "mma.sync.aligned.m16n8k8.row.col.f32.tf32.tf32.f32 "
                        "{%0,%1,%2,%3}, {%4,%5,%6,%7}, {%8,%9}, {%0,%1,%2,%3};\n"
                        : "+f"(acc[mi][ni][0]), "+f"(acc[mi][ni][1]),
                          "+f"(acc[mi][ni][2]), "+f"(acc[mi][ni][3])
                        : "r"(a[mi][0]), "r"(a[mi][1]), "r"(a[mi][2]), "r"(a[mi][3]),
                          "r"(b0), "r"(b1));
                }
            }
        }
        __syncthreads();
    }
#undef ISSUE_TILE

#pragma unroll
    for (int mi = 0; mi < 2; mi++) {
#pragma unroll
        for (int ni = 0; ni < 4; ni++) {
            int r = row0 + wm + mi * 16 + gID;
            int cb = col0 + wn + ni * 8 + tg * 2;
            float bv0 = 0.f, bv1 = 0.f;
            if (bias) { bv0 = bias[cb]; bv1 = bias[cb + 1]; }
#pragma unroll
            for (int half = 0; half < 2; half++) {
                int gr = r + half * 8;
                if (gr >= M) continue;
                float v0 = acc[mi][ni][half * 2 + 0] + bv0;
                float v1 = acc[mi][ni][half * 2 + 1] + bv1;
                if (EPI == 1) { v0 *= scale; v1 *= scale; }
                if (EPI == 2) {
                    v0 = 0.5f * v0 * (1.0f + erff(v0 * 0.70710678118654752f));
                    v1 = 0.5f * v1 * (1.0f + erff(v1 * 0.70710678118654752f));
                }
                *reinterpret_cast<float2*>(&C[(long)gr * ldc + cb]) = make_float2(v0, v1);
            }
        }
    }
}

// ---------------- folded attention weights for ALL layers -------------------
// grid (2, NL): x=0 -> src, x=1 -> dst. 256 threads: k = tid>>2, j = tid&3.
__global__ void watt_prep_kernel(const float* __restrict__ Wc,
                                 const float* __restrict__ att_s,
                                 const float* __restrict__ att_d)
{
    int tid = threadIdx.x;
    int k = tid >> 2, j = tid & 3;
    int l = blockIdx.y;
    const float* att = ((blockIdx.x == 0) ? att_s : att_d) + (long)l * NH * CD;
    const float* wr = Wc + (long)l * HID * HC + (long)k * HC + j * CD;
    const float* ar = att + j * CD;
    float s = 0.f;
#pragma unroll 8
    for (int c = 0; c < CD; c++) s = fmaf(wr[c], ar[c], s);
    g_watt[l * HID * 8 + k * 8 + blockIdx.x * 4 + j] = s;
}

// ---------------- scores from h (standalone, layer 0) -----------------------
__global__ void scores_kernel(const float* __restrict__ h,
                              const float* __restrict__ watt)
{
    int n = (blockIdx.x * blockDim.x + threadIdx.x) >> 5;
    if (n >= N_NODES) return;
    int lane = threadIdx.x & 31;
    float2 hv = *reinterpret_cast<const float2*>(&h[(long)n * HID + lane * 2]);
    int k0 = lane * 2;
    float4 s0 = *reinterpret_cast<const float4*>(&watt[k0 * 8]);
    float4 d0 = *reinterpret_cast<const float4*>(&watt[k0 * 8 + 4]);
    float4 s1 = *reinterpret_cast<const float4*>(&watt[k0 * 8 + 8]);
    float4 d1 = *reinterpret_cast<const float4*>(&watt[k0 * 8 + 12]);
    float v[8];
    v[0] = hv.x * s0.x + hv.y * s1.x;
    v[1] = hv.x * s0.y + hv.y * s1.y;
    v[2] = hv.x * s0.z + hv.y * s1.z;
    v[3] = hv.x * s0.w + hv.y * s1.w;
    v[4] = hv.x * d0.x + hv.y * d1.x;
    v[5] = hv.x * d0.y + hv.y * d1.y;
    v[6] = hv.x * d0.z + hv.y * d1.z;
    v[7] = hv.x * d0.w + hv.y * d1.w;
#pragma unroll
    for (int j = 0; j < 8; j++)
#pragma unroll
        for (int o = 16; o > 0; o >>= 1)
            v[j] += __shfl_xor_sync(0xffffffffu, v[j], o);
    if (lane == 0) {
        *reinterpret_cast<float4*>(&g_as[n * 4]) = make_float4(v[0], v[1], v[2], v[3]);
        *reinterpret_cast<float4*>(&g_ad[n * 4]) = make_float4(v[4], v[5], v[6], v[7]);
    }
}

__device__ __forceinline__ float lrelu(float x) { return x > 0.f ? x : 0.2f * x; }

// ---------------- segment softmax (2 passes; 1/z folded into agg) ----------
__global__ void softmax_kernel()
{
    int d = (blockIdx.x * blockDim.x + threadIdx.x) >> 5;
    if (d >= N_NODES) return;
    int lane = threadIdx.x & 31;
    int beg = g_off[d], end = g_off[d + 1];
    float4 ad = *reinterpret_cast<const float4*>(g_ad + d * 4);

    float m0 = -INFINITY, m1 = -INFINITY, m2 = -INFINITY, m3 = -INFINITY;
    for (int p = beg + lane; p < end; p += 32) {
        int s = g_srt_src[p];
        float4 as = *reinterpret_cast<const float4*>(g_as + s * 4);
        m0 = fmaxf(m0, lrelu(as.x + ad.x));
        m1 = fmaxf(m1, lrelu(as.y + ad.y));
        m2 = fmaxf(m2, lrelu(as.z + ad.z));
        m3 = fmaxf(m3, lrelu(as.w + ad.w));
    }
#pragma unroll
    for (int o = 16; o > 0; o >>= 1) {
        m0 = fmaxf(m0, __shfl_xor_sync(0xffffffffu, m0, o));
        m1 = fmaxf(m1, __shfl_xor_sync(0xffffffffu, m1, o));
        m2 = fmaxf(m2, __shfl_xor_sync(0xffffffffu, m2, o));
        m3 = fmaxf(m3, __shfl_xor_sync(0xffffffffu, m3, o));
    }
    float z0 = 0.f, z1 = 0.f, z2 = 0.f, z3 = 0.f;
    for (int p = beg + lane; p < end; p += 32) {
        int s = g_srt_src[p];
        float4 as = *reinterpret_cast<const float4*>(g_as + s * 4);
        float4 ex;
        ex.x = expf(lrelu(as.x + ad.x) - m0);
        ex.y = expf(lrelu(as.y + ad.y) - m1);
        ex.z = expf(lrelu(as.z + ad.z) - m2);
        ex.w = expf(lrelu(as.w + ad.w) - m3);
        *reinterpret_cast<float4*>(g_alpha + (long)p * 4) = ex;
        z0 += ex.x; z1 += ex.y; z2 += ex.z; z3 += ex.w;
    }
#pragma unroll
    for (int o = 16; o > 0; o >>= 1) {
        z0 += __shfl_xor_sync(0xffffffffu, z0, o);
        z1 += __shfl_xor_sync(0xffffffffu, z1, o);
        z2 += __shfl_xor_sync(0xffffffffu, z2, o);
        z3 += __shfl_xor_sync(0xffffffffu, z3, o);
    }
    if (lane == 0) {
        *reinterpret_cast<float4*>(&g_rz[d * 4]) =
            make_float4(1.f / (z0 + 1e-16f), 1.f / (z1 + 1e-16f),
                        1.f / (z2 + 1e-16f), 1.f / (z3 + 1e-16f));
    }
}

// ---------------- aggregation of h (warp per dst): ah[d,h,:]=Σ α·h[src] ----
__global__ __launch_bounds__(256) void agg_h_kernel(const float* __restrict__ h,
                                                    float* __restrict__ ah)
{
    int d = (blockIdx.x * blockDim.x + threadIdx.x) >> 5;
    if (d >= N_NODES) return;
    int lane = threadIdx.x & 31;
    int beg = g_off[d], end = g_off[d + 1];

    float2 a0 = make_float2(0.f, 0.f), a1 = a0, a2 = a0, a3 = a0;
    int p = beg;
    for (; p + 1 < end; p += 2) {
        int s0 = g_srt_src[p];
        int s1 = g_srt_src[p + 1];
        float4 al0 = *reinterpret_cast<const float4*>(&g_alpha[(long)p * 4]);
        float4 al1 = *reinterpret_cast<const float4*>(&g_alpha[(long)(p + 1) * 4]);
        float2 h0 = *reinterpret_cast<const float2*>(&h[(long)s0 * HID + lane * 2]);
        float2 h1 = *reinterpret_cast<const float2*>(&h[(long)s1 * HID + lane * 2]);
        a0.x = fmaf(al0.x, h0.x, a0.x); a0.y = fmaf(al0.x, h0.y, a0.y);
        a1.x = fmaf(al0.y, h0.x, a1.x); a1.y = fmaf(al0.y, h0.y, a1.y);
        a2.x = fmaf(al0.z, h0.x, a2.x); a2.y = fmaf(al0.z, h0.y, a2.y);
        a3.x = fmaf(al0.w, h0.x, a3.x); a3.y = fmaf(al0.w, h0.y, a3.y);
        a0.x = fmaf(al1.x, h1.x, a0.x); a0.y = fmaf(al1.x, h1.y, a0.y);
        a1.x = fmaf(al1.y, h1.x, a1.x); a1.y = fmaf(al1.y, h1.y, a1.y);
        a2.x = fmaf(al1.z, h1.x, a2.x); a2.y = fmaf(al1.z, h1.y, a2.y);
        a3.x = fmaf(al1.w, h1.x, a3.x); a3.y = fmaf(al1.w, h1.y, a3.y);
    }
    if (p < end) {
        int s0 = g_srt_src[p];
        float4 al0 = *reinterpret_cast<const float4*>(&g_alpha[(long)p * 4]);
        float2 h0 = *reinterpret_cast<const float2*>(&h[(long)s0 * HID + lane * 2]);
        a0.x = fmaf(al0.x, h0.x, a0.x); a0.y = fmaf(al0.x, h0.y, a0.y);
        a1.x = fmaf(al0.y, h0.x, a1.x); a1.y = fmaf(al0.y, h0.y, a1.y);
        a2.x = fmaf(al0.z, h0.x, a2.x); a2.y = fmaf(al0.z, h0.y, a2.y);
        a3.x = fmaf(al0.w, h0.x, a3.x); a3.y = fmaf(al0.w, h0.y, a3.y);
    }
    float4 rz = *reinterpret_cast<const float4*>(&g_rz[d * 4]);
    a0.x *= rz.x; a0.y *= rz.x;
    a1.x *= rz.y; a1.y *= rz.y;
    a2.x *= rz.z; a2.y *= rz.z;
    a3.x *= rz.w; a3.y *= rz.w;
    long base = (long)d * HC + lane * 2;
    *reinterpret_cast<float2*>(&ah[base + 0 * CD]) = a0;
    *reinterpret_cast<float2*>(&ah[base + 1 * CD]) = a1;
    *reinterpret_cast<float2*>(&ah[base + 2 * CD]) = a2;
    *reinterpret_cast<float2*>(&ah[base + 3 * CD]) = a3;
}

// ------- layernorm + residual (+ fused next-layer scores) (warp per node) ---
__global__ void ln_kernel(const float* __restrict__ f,
                          const float* __restrict__ gam,
                          const float* __restrict__ bet,
                          float* __restrict__ h,
                          const float* __restrict__ watt)
{
    int node = (blockIdx.x * blockDim.x + threadIdx.x) >> 5;
    if (node >= N_NODES) return;
    int lane = threadIdx.x & 31;
    float v0 = f[(long)node * HID + lane];
    float v1 = f[(long)node * HID + 32 + lane];
    float s = v0 + v1;
#pragma unroll
    for (int o = 16; o > 0; o >>= 1) s += __shfl_xor_sync(0xffffffffu, s, o);
    float mean = s * (1.f / 64.f);
    float d0 = v0 - mean, d1 = v1 - mean;
    float vv = d0 * d0 + d1 * d1;
#pragma unroll
    for (int o = 16; o > 0; o >>= 1) vv += __shfl_xor_sync(0xffffffffu, vv, o);
    float rstd = rsqrtf(vv * (1.f / 64.f) + 1e-5f);
    float o0 = h[(long)node * HID + lane]      + d0 * rstd * gam[lane]      + bet[lane];
    float o1 = h[(long)node * HID + 32 + lane] + d1 * rstd * gam[32 + lane] + bet[32 + lane];
    h[(long)node * HID + lane]      = o0;
    h[(long)node * HID + 32 + lane] = o1;

    if (watt) {
        // this lane holds h[lane] (=o0) and h[lane+32] (=o1)
        float4 s0 = *reinterpret_cast<const float4*>(&watt[lane * 8]);
        float4 dd0 = *reinterpret_cast<const float4*>(&watt[lane * 8 + 4]);
        float4 s1 = *reinterpret_cast<const float4*>(&watt[(lane + 32) * 8]);
        float4 dd1 = *reinterpret_cast<const float4*>(&watt[(lane + 32) * 8 + 4]);
        float v[8];
        v[0] = o0 * s0.x + o1 * s1.x;
        v[1] = o0 * s0.y + o1 * s1.y;
        v[2] = o0 * s0.z + o1 * s1.z;
        v[3] = o0 * s0.w + o1 * s1.w;
        v[4] = o0 * dd0.x + o1 * dd1.x;
        v[5] = o0 * dd0.y + o1 * dd1.y;
        v[6] = o0 * dd0.z + o1 * dd1.z;
        v[7] = o0 * dd0.w + o1 * dd1.w;
#pragma unroll
        for (int j = 0; j < 8; j++)
#pragma unroll
            for (int o = 16; o > 0; o >>= 1)
                v[j] += __shfl_xor_sync(0xffffffffu, v[j], o);
        if (lane == 0) {
            *reinterpret_cast<float4*>(&g_as[node * 4]) = make_float4(v[0], v[1], v[2], v[3]);
            *reinterpret_cast<float4*>(&g_ad[node * 4]) = make_float4(v[4], v[5], v[6], v[7]);
        }
    }
}

// ---------------- driver -----------------------------------------------------
extern "C" void kernel_launch(void* const* d_in, const int* in_sizes, int n_in,
                              void* d_out, int out_size)
{
    const float* x     = (const float*)d_in[0];
    const int*   ei    = (const int*)  d_in[1];
    const float* We    = (const float*)d_in[2];
    const float* be    = (const float*)d_in[3];
    const float* Wc    = (const float*)d_in[4];
    const float* att_s = (const float*)d_in[5];
    const float* att_d = (const float*)d_in[6];
    const float* bc    = (const float*)d_in[7];
    const float* W1    = (const float*)d_in[8];
    const float* b1    = (const float*)d_in[9];
    const float* W2    = (const float*)d_in[10];
    const float* b2    = (const float*)d_in[11];
    const float* lng   = (const float*)d_in[12];
    const float* lnb   = (const float*)d_in[13];
    float* h = (float*)d_out;

    float *p_xh, *p_out, *p_f1, *p_watt;
    cudaGetSymbolAddress((void**)&p_xh,   g_xh);
    cudaGetSymbolAddress((void**)&p_out,  g_out);
    cudaGetSymbolAddress((void**)&p_f1,   g_f1);
    cudaGetSymbolAddress((void**)&p_watt, g_watt);

    // ---- folded attention weights for all layers (independent of h) ----
    watt_prep_kernel<<<dim3(2, NL), 256>>>(Wc, att_s, att_d);

    // ---- CSR build (once; reused across layers) ----
    zero_cnt_kernel<<<(N_NODES + 255) / 256, 256>>>();
    hist_kernel<<<(EN + 255) / 256, 256>>>(ei);
    scan_kernel<<<1, 1024>>>();
    scatter_kernel<<<(EN + 255) / 256, 256>>>(ei);

    const int GY = (N_NODES + 127) / 128;
    const int WG = (N_NODES * 32 + 255) / 256;   // warp-per-node grids

    // ---- embed: h = (x @ We + be) * 8 ----
    mma_gemm_kernel<1><<<dim3(1, GY), 256>>>(x, We, be, h,
                                             N_NODES, HID, IN_DIM,
                                             IN_DIM, HID, HID, 0, 8.0f);
    // scores for layer 0
    scores_kernel<<<WG, 256>>>(h, p_watt);

    for (int l = 0; l < NL; l++) {
        const float* Wc_l = Wc + (long)l * HID * HC;
        // edge softmax (unnormalized alpha + 1/z)
        softmax_kernel<<<WG, 256>>>();
        // aggregate h per head -> g_xh used as ah buffer
        agg_h_kernel<<<WG, 256>>>(h, p_xh);
        // project per head: out[:, hd*64:+64] = ah[:, hd*64:+64] @ Wc_l[hd] + bc
        mma_gemm_kernel<0><<<dim3(NH, GY), 256>>>(p_xh, Wc_l, bc + l * HC, p_out,
                                                  N_NODES, CD, HID,
                                                  HC, HC, HC, CD, 0.f);
        // f1 = gelu(out @ W1[l] + b1[l])
        mma_gemm_kernel<2><<<dim3(DFF / 64, GY), 256>>>(p_out, W1 + (long)l * HC * DFF,
                                                        b1 + l * DFF, p_f1,
                                                        N_NODES, DFF, HC,
                                                        HC, DFF, DFF, 0, 0.f);
        // f2 = f1 @ W2[l] + b2[l]  (reuse g_xh as f2 buffer)
        mma_gemm_kernel<0><<<dim3(1, GY), 256>>>(p_f1, W2 + (long)l * DFF * HID,
                                                 b2 + l * HID, p_xh,
                                                 N_NODES, HID, DFF,
                                                 DFF, HID, HID, 0, 0.f);
        // h += layernorm(f2); fused scores for next layer
        const float* watt_next = (l + 1 < NL) ? (p_watt + (l + 1) * HID * 8) : nullptr;
        ln_kernel<<<WG, 256>>>(p_xh, lng + l * HID, lnb + l * HID, h, watt_next);
    }
    (void)in_sizes; (void)n_in; (void)out_size;
}

// round 8
// speedup vs baseline: 2.0855x; 1.1067x over previous
#include <cuda_runtime.h>
#include <math.h>
#include <stdint.h>

#define N_NODES 20000
#define E_EDGES 320000
#define EN      340000   // E + N self loops
#define IN_DIM  256
#define HID     64
#define NH      4
#define CD      64
#define HC      256      // NH*CD
#define DFF     128
#define NL      4

#define SCAN_NB 79       // ceil(20000/256)

// ---------------- scratch (module-global device memory; no runtime alloc) ----
__device__ __align__(16) float g_xh[N_NODES * HC];      // f2 buffer / aggregated-h buffer
__device__ __align__(16) float g_as[N_NODES * NH];      // attention src scores
__device__ __align__(16) float g_ad[N_NODES * NH];      // attention dst scores
__device__ __align__(16) float g_watt[NL * HID * 8];    // per-layer ws_hat/wd_hat
__device__ int   g_srt_src[EN];
__device__ int   g_cnt[N_NODES];
__device__ int   g_off[N_NODES + 1];
__device__ int   g_cur[N_NODES];
__device__ int   g_bsum[SCAN_NB];
__device__ int   g_bpre[SCAN_NB];
__device__ __align__(16) float g_out[N_NODES * HC];     // projected messages
__device__ __align__(16) float g_f1[N_NODES * DFF];     // FFN hidden

// ---------------- CSR build ----------------
__global__ void zero_cnt_kernel() {
    int i = blockIdx.x * blockDim.x + threadIdx.x;
    if (i < N_NODES) g_cnt[i] = 0;
}

__global__ void hist_kernel(const int* __restrict__ ei) {
    int i = blockIdx.x * blockDim.x + threadIdx.x;
    if (i >= EN) return;
    int d = (i < E_EDGES) ? ei[E_EDGES + i] : (i - E_EDGES);
    atomicAdd(&g_cnt[d], 1);
}

// phase 1: per-block exclusive scan of 256 counts; block total -> g_bsum
__global__ __launch_bounds__(256) void scan1_kernel() {
    __shared__ int ws[8];
    int t = threadIdx.x, b = blockIdx.x;
    int i = b * 256 + t;
    int v = (i < N_NODES) ? g_cnt[i] : 0;
    int lane = t & 31, w = t >> 5;
    // warp inclusive scan
    int x = v;
#pragma unroll
    for (int o = 1; o < 32; o <<= 1) {
        int y = __shfl_up_sync(0xffffffffu, x, o);
        if (lane >= o) x += y;
    }
    if (lane == 31) ws[w] = x;
    __syncthreads();
    if (t < 8) {
        int y = ws[t];
#pragma unroll
        for (int o = 1; o < 8; o <<= 1) {
            int z = __shfl_up_sync(0xffu, y, o);
            if (t >= o) y += z;
        }
        ws[t] = y;
    }
    __syncthreads();
    int incl = x + (w > 0 ? ws[w - 1] : 0);
    int excl = incl - v;
    if (i < N_NODES) g_off[i] = excl;           // block-local exclusive (fixed in phase 3)
    if (t == 255) g_bsum[b] = incl;
}

// phase 2: scan the 79 block sums (single block)
__global__ void scan2_kernel() {
    __shared__ int s[128];
    int t = threadIdx.x;
    s[t] = (t < SCAN_NB) ? g_bsum[t] : 0;
    __syncthreads();
#pragma unroll
    for (int o = 1; o < 128; o <<= 1) {
        int v = (t >= o) ? s[t - o] : 0;
        __syncthreads();
        s[t] += v;
        __syncthreads();
    }
    if (t < SCAN_NB) g_bpre[t] = (t > 0) ? s[t - 1] : 0;   // exclusive prefix
}

// phase 3: add block prefix, fill g_cur, set sentinel
__global__ __launch_bounds__(256) void scan3_kernel() {
    int t = threadIdx.x, b = blockIdx.x;
    int i = b * 256 + t;
    if (i < N_NODES) {
        int v = g_off[i] + g_bpre[b];
        g_off[i] = v;
        g_cur[i] = v;
    }
    if (i == 0) g_off[N_NODES] = EN;
}

__global__ void scatter_kernel(const int* __restrict__ ei) {
    int i = blockIdx.x * blockDim.x + threadIdx.x;
    if (i >= EN) return;
    int s, d;
    if (i < E_EDGES) { s = ei[i]; d = ei[E_EDGES + i]; }
    else             { s = d = i - E_EDGES; }
    int pos = atomicAdd(&g_cur[d], 1);
    g_srt_src[pos] = s;
}

// ---------------- tf32 tensor-core GEMM, cp.async 2-stage -------------------
__device__ __forceinline__ uint32_t f2tf32(float f) {
    uint32_t u;
    asm("cvt.rna.tf32.f32 %0, %1;" : "=r"(u) : "f"(f));
    return u;
}

template <int EPI>
__global__ __launch_bounds__(256) void mma_gemm_kernel(
    const float* __restrict__ A, const float* __restrict__ B,
    const float* __restrict__ bias, float* __restrict__ C,
    int M, int N, int K, int lda, int ldb, int ldc, int koff, float scale)
{
    const int BM = 128, BN = 64, BK = 16;
    __shared__ __align__(16) float As[2][BM][BK + 4];
    __shared__ __align__(16) float Bs[2][BK][BN + 8];

    int tid = threadIdx.x;
    int lane = tid & 31;
    int w = tid >> 5;
    int wm = (w & 3) * 32;
    int wn = (w >> 2) * 32;
    int gID = lane >> 2;
    int tg  = lane & 3;
    int row0 = blockIdx.y * BM, col0 = blockIdx.x * BN;
    int akoff = koff * blockIdx.x;

    int am  = tid >> 2;
    int ak4 = (tid & 3) * 4;
    int bk  = tid >> 4;
    int bn4 = (tid & 15) * 4;

    float acc[2][4][4];
#pragma unroll
    for (int mi = 0; mi < 2; mi++)
#pragma unroll
        for (int ni = 0; ni < 4; ni++)
#pragma unroll
            for (int r = 0; r < 4; r++) acc[mi][ni][r] = 0.f;

    const int niter = K / BK;

#define ISSUE_TILE(IT, BUF)                                                     \
    {                                                                           \
        int kk_ = (IT) * BK;                                                    \
        _Pragma("unroll")                                                       \
        for (int t = 0; t < 2; t++) {                                           \
            int m_ = am + t * 64;                                               \
            int gm_ = row0 + m_;                                                \
            const float* src_ = &A[(long)gm_ * lda + akoff + kk_ + ak4];        \
            uint32_t dst_ = (uint32_t)__cvta_generic_to_shared(&As[BUF][m_][ak4]); \
            int sz_ = (gm_ < M) ? 16 : 0;                                       \
            asm volatile("cp.async.cg.shared.global [%0], [%1], 16, %2;\n"      \
                         :: "r"(dst_), "l"(src_), "r"(sz_));                    \
        }                                                                       \
        {                                                                       \
            const float* src_ = &B[(long)(kk_ + bk) * ldb + col0 + bn4];        \
            uint32_t dst_ = (uint32_t)__cvta_generic_to_shared(&Bs[BUF][bk][bn4]); \
            asm volatile("cp.async.cg.shared.global [%0], [%1], 16, 16;\n"      \
                         :: "r"(dst_), "l"(src_));                              \
        }                                                                       \
        asm volatile("cp.async.commit_group;\n");                               \
    }

    ISSUE_TILE(0, 0);

    for (int it = 0; it < niter; it++) {
        int buf = it & 1;
        asm volatile("cp.async.wait_group 0;\n");
        __syncthreads();
        if (it + 1 < niter) ISSUE_TILE(it + 1, (it + 1) & 1);

#pragma unroll
        for (int ks = 0; ks < 2; ks++) {
            int k0 = ks * 8;
            uint32_t a[2][4];
#pragma unroll
            for (int mi = 0; mi < 2; mi++) {
                int r = wm + mi * 16;
                a[mi][0] = f2tf32(As[buf][r + gID][k0 + tg]);
                a[mi][1] = f2tf32(As[buf][r + gID + 8][k0 + tg]);
                a[mi][2] = f2tf32(As[buf][r + gID][k0 + tg + 4]);
                a[mi][3] = f2tf32(As[buf][r + gID + 8][k0 + tg + 4]);
            }
#pragma unroll
            for (int ni = 0; ni < 4; ni++) {
                uint32_t b0 = f2tf32(Bs[buf][k0 + tg][wn + ni * 8 + gID]);
                uint32_t b1 = f2tf32(Bs[buf][k0 + tg + 4][wn + ni * 8 + gID]);
#pragma unroll
                for (int mi = 0; mi < 2; mi++) {
                    asm volatile(
                        "mma.sync.aligned.m16n8k8.row.col.f32.tf32.tf32.f32 "
                        "{%0,%1,%2,%3}, {%4,%5,%6,%7}, {%8,%9}, {%0,%1,%2,%3};\n"
                        : "+f"(acc[mi][ni][0]), "+f"(acc[mi][ni][1]),
                          "+f"(acc[mi][ni][2]), "+f"(acc[mi][ni][3])
                        : "r"(a[mi][0]), "r"(a[mi][1]), "r"(a[mi][2]), "r"(a[mi][3]),
                          "r"(b0), "r"(b1));
                }
            }
        }
        __syncthreads();
    }
#undef ISSUE_TILE

#pragma unroll
    for (int mi = 0; mi < 2; mi++) {
#pragma unroll
        for (int ni = 0; ni < 4; ni++) {
            int r = row0 + wm + mi * 16 + gID;
            int cb = col0 + wn + ni * 8 + tg * 2;
            float bv0 = 0.f, bv1 = 0.f;
            if (bias) { bv0 = bias[cb]; bv1 = bias[cb + 1]; }
#pragma unroll
            for (int half = 0; half < 2; half++) {
                int gr = r + half * 8;
                if (gr >= M) continue;
                float v0 = acc[mi][ni][half * 2 + 0] + bv0;
                float v1 = acc[mi][ni][half * 2 + 1] + bv1;
                if (EPI == 1) { v0 *= scale; v1 *= scale; }
                if (EPI == 2) {
                    v0 = 0.5f * v0 * (1.0f + erff(v0 * 0.70710678118654752f));
                    v1 = 0.5f * v1 * (1.0f + erff(v1 * 0.70710678118654752f));
                }
                *reinterpret_cast<float2*>(&C[(long)gr * ldc + cb]) = make_float2(v0, v1);
            }
        }
    }
}

// ---------------- folded attention weights for ALL layers -------------------
__global__ void watt_prep_kernel(const float* __restrict__ Wc,
                                 const float* __restrict__ att_s,
                                 const float* __restrict__ att_d)
{
    int tid = threadIdx.x;
    int k = tid >> 2, j = tid & 3;
    int l = blockIdx.y;
    const float* att = ((blockIdx.x == 0) ? att_s : att_d) + (long)l * NH * CD;
    const float* wr = Wc + (long)l * HID * HC + (long)k * HC + j * CD;
    const float* ar = att + j * CD;
    float s = 0.f;
#pragma unroll 8
    for (int c = 0; c < CD; c++) s = fmaf(wr[c], ar[c], s);
    g_watt[l * HID * 8 + k * 8 + blockIdx.x * 4 + j] = s;
}

// ---------------- scores from h (standalone, layer 0) -----------------------
__global__ void scores_kernel(const float* __restrict__ h,
                              const float* __restrict__ watt)
{
    int n = (blockIdx.x * blockDim.x + threadIdx.x) >> 5;
    if (n >= N_NODES) return;
    int lane = threadIdx.x & 31;
    float2 hv = *reinterpret_cast<const float2*>(&h[(long)n * HID + lane * 2]);
    int k0 = lane * 2;
    float4 s0 = *reinterpret_cast<const float4*>(&watt[k0 * 8]);
    float4 d0 = *reinterpret_cast<const float4*>(&watt[k0 * 8 + 4]);
    float4 s1 = *reinterpret_cast<const float4*>(&watt[k0 * 8 + 8]);
    float4 d1 = *reinterpret_cast<const float4*>(&watt[k0 * 8 + 12]);
    float v[8];
    v[0] = hv.x * s0.x + hv.y * s1.x;
    v[1] = hv.x * s0.y + hv.y * s1.y;
    v[2] = hv.x * s0.z + hv.y * s1.z;
    v[3] = hv.x * s0.w + hv.y * s1.w;
    v[4] = hv.x * d0.x + hv.y * d1.x;
    v[5] = hv.x * d0.y + hv.y * d1.y;
    v[6] = hv.x * d0.z + hv.y * d1.z;
    v[7] = hv.x * d0.w + hv.y * d1.w;
#pragma unroll
    for (int j = 0; j < 8; j++)
#pragma unroll
        for (int o = 16; o > 0; o >>= 1)
            v[j] += __shfl_xor_sync(0xffffffffu, v[j], o);
    if (lane == 0) {
        *reinterpret_cast<float4*>(&g_as[n * 4]) = make_float4(v[0], v[1], v[2], v[3]);
        *reinterpret_cast<float4*>(&g_ad[n * 4]) = make_float4(v[4], v[5], v[6], v[7]);
    }
}

__device__ __forceinline__ float lrelu(float x) { return x > 0.f ? x : 0.2f * x; }

// ------ fused softmax + aggregation (warp per dst, no alpha array) ----------
// lrelu is monotone -> max_p lrelu(as_p+ad) = lrelu(max_p as_p + ad).
__global__ __launch_bounds__(256) void agg_fused_kernel(const float* __restrict__ h,
                                                        float* __restrict__ ah)
{
    int d = (blockIdx.x * blockDim.x + threadIdx.x) >> 5;
    if (d >= N_NODES) return;
    int lane = threadIdx.x & 31;
    int beg = g_off[d], end = g_off[d + 1];
    float4 ad = *reinterpret_cast<const float4*>(g_ad + d * 4);

    // pass 1: warp max of as
    float m0 = -INFINITY, m1 = -INFINITY, m2 = -INFINITY, m3 = -INFINITY;
    for (int p = beg + lane; p < end; p += 32) {
        int s = g_srt_src[p];
        float4 as = *reinterpret_cast<const float4*>(g_as + s * 4);
        m0 = fmaxf(m0, as.x); m1 = fmaxf(m1, as.y);
        m2 = fmaxf(m2, as.z); m3 = fmaxf(m3, as.w);
    }
#pragma unroll
    for (int o = 16; o > 0; o >>= 1) {
        m0 = fmaxf(m0, __shfl_xor_sync(0xffffffffu, m0, o));
        m1 = fmaxf(m1, __shfl_xor_sync(0xffffffffu, m1, o));
        m2 = fmaxf(m2, __shfl_xor_sync(0xffffffffu, m2, o));
        m3 = fmaxf(m3, __shfl_xor_sync(0xffffffffu, m3, o));
    }
    m0 = lrelu(m0 + ad.x); m1 = lrelu(m1 + ad.y);
    m2 = lrelu(m2 + ad.z); m3 = lrelu(m3 + ad.w);

    // pass 2: exp + broadcast + gather-FMA
    float2 a0 = make_float2(0.f, 0.f), a1 = a0, a2 = a0, a3 = a0;
    float z0 = 0.f, z1 = 0.f, z2 = 0.f, z3 = 0.f;
    for (int base = beg; base < end; base += 32) {
        int p = base + lane;
        bool valid = p < end;
        int s = valid ? g_srt_src[p] : 0;
        float4 as = *reinterpret_cast<const float4*>(g_as + s * 4);
        float e0 = 0.f, e1 = 0.f, e2 = 0.f, e3 = 0.f;
        if (valid) {
            e0 = expf(lrelu(as.x + ad.x) - m0);
            e1 = expf(lrelu(as.y + ad.y) - m1);
            e2 = expf(lrelu(as.z + ad.z) - m2);
            e3 = expf(lrelu(as.w + ad.w) - m3);
            z0 += e0; z1 += e1; z2 += e2; z3 += e3;
        }
        int nn = min(32, end - base);
        for (int i = 0; i < nn; i++) {
            int   si = __shfl_sync(0xffffffffu, s, i);
            float b0 = __shfl_sync(0xffffffffu, e0, i);
            float b1 = __shfl_sync(0xffffffffu, e1, i);
            float b2 = __shfl_sync(0xffffffffu, e2, i);
            float b3 = __shfl_sync(0xffffffffu, e3, i);
            float2 hv = *reinterpret_cast<const float2*>(&h[(long)si * HID + lane * 2]);
            a0.x = fmaf(b0, hv.x, a0.x); a0.y = fmaf(b0, hv.y, a0.y);
            a1.x = fmaf(b1, hv.x, a1.x); a1.y = fmaf(b1, hv.y, a1.y);
            a2.x = fmaf(b2, hv.x, a2.x); a2.y = fmaf(b2, hv.y, a2.y);
            a3.x = fmaf(b3, hv.x, a3.x); a3.y = fmaf(b3, hv.y, a3.y);
        }
    }
#pragma unroll
    for (int o = 16; o > 0; o >>= 1) {
        z0 += __shfl_xor_sync(0xffffffffu, z0, o);
        z1 += __shfl_xor_sync(0xffffffffu, z1, o);
        z2 += __shfl_xor_sync(0xffffffffu, z2, o);
        z3 += __shfl_xor_sync(0xffffffffu, z3, o);
    }
    float r0 = 1.f / (z0 + 1e-16f), r1 = 1.f / (z1 + 1e-16f);
    float r2 = 1.f / (z2 + 1e-16f), r3 = 1.f / (z3 + 1e-16f);
    a0.x *= r0; a0.y *= r0;
    a1.x *= r1; a1.y *= r1;
    a2.x *= r2; a2.y *= r2;
    a3.x *= r3; a3.y *= r3;
    long basep = (long)d * HC + lane * 2;
    *reinterpret_cast<float2*>(&ah[basep + 0 * CD]) = a0;
    *reinterpret_cast<float2*>(&ah[basep + 1 * CD]) = a1;
    *reinterpret_cast<float2*>(&ah[basep + 2 * CD]) = a2;
    *reinterpret_cast<float2*>(&ah[basep + 3 * CD]) = a3;
}

// ------- layernorm + residual (+ fused next-layer scores) (warp per node) ---
__global__ void ln_kernel(const float* __restrict__ f,
                          const float* __restrict__ gam,
                          const float* __restrict__ bet,
                          float* __restrict__ h,
                          const float* __restrict__ watt)
{
    int node = (blockIdx.x * blockDim.x + threadIdx.x) >> 5;
    if (node >= N_NODES) return;
    int lane = threadIdx.x & 31;
    float v0 = f[(long)node * HID + lane];
    float v1 = f[(long)node * HID + 32 + lane];
    float s = v0 + v1;
#pragma unroll
    for (int o = 16; o > 0; o >>= 1) s += __shfl_xor_sync(0xffffffffu, s, o);
    float mean = s * (1.f / 64.f);
    float d0 = v0 - mean, d1 = v1 - mean;
    float vv = d0 * d0 + d1 * d1;
#pragma unroll
    for (int o = 16; o > 0; o >>= 1) vv += __shfl_xor_sync(0xffffffffu, vv, o);
    float rstd = rsqrtf(vv * (1.f / 64.f) + 1e-5f);
    float o0 = h[(long)node * HID + lane]      + d0 * rstd * gam[lane]      + bet[lane];
    float o1 = h[(long)node * HID + 32 + lane] + d1 * rstd * gam[32 + lane] + bet[32 + lane];
    h[(long)node * HID + lane]      = o0;
    h[(long)node * HID + 32 + lane] = o1;

    if (watt) {
        float4 s0 = *reinterpret_cast<const float4*>(&watt[lane * 8]);
        float4 dd0 = *reinterpret_cast<const float4*>(&watt[lane * 8 + 4]);
        float4 s1 = *reinterpret_cast<const float4*>(&watt[(lane + 32) * 8]);
        float4 dd1 = *reinterpret_cast<const float4*>(&watt[(lane + 32) * 8 + 4]);
        float v[8];
        v[0] = o0 * s0.x + o1 * s1.x;
        v[1] = o0 * s0.y + o1 * s1.y;
        v[2] = o0 * s0.z + o1 * s1.z;
        v[3] = o0 * s0.w + o1 * s1.w;
        v[4] = o0 * dd0.x + o1 * dd1.x;
        v[5] = o0 * dd0.y + o1 * dd1.y;
        v[6] = o0 * dd0.z + o1 * dd1.z;
        v[7] = o0 * dd0.w + o1 * dd1.w;
#pragma unroll
        for (int j = 0; j < 8; j++)
#pragma unroll
            for (int o = 16; o > 0; o >>= 1)
                v[j] += __shfl_xor_sync(0xffffffffu, v[j], o);
        if (lane == 0) {
            *reinterpret_cast<float4*>(&g_as[node * 4]) = make_float4(v[0], v[1], v[2], v[3]);
            *reinterpret_cast<float4*>(&g_ad[node * 4]) = make_float4(v[4], v[5], v[6], v[7]);
        }
    }
}

// ---------------- driver -----------------------------------------------------
extern "C" void kernel_launch(void* const* d_in, const int* in_sizes, int n_in,
                              void* d_out, int out_size)
{
    const float* x     = (const float*)d_in[0];
    const int*   ei    = (const int*)  d_in[1];
    const float* We    = (const float*)d_in[2];
    const float* be    = (const float*)d_in[3];
    const float* Wc    = (const float*)d_in[4];
    const float* att_s = (const float*)d_in[5];
    const float* att_d = (const float*)d_in[6];
    const float* bc    = (const float*)d_in[7];
    const float* W1    = (const float*)d_in[8];
    const float* b1    = (const float*)d_in[9];
    const float* W2    = (const float*)d_in[10];
    const float* b2    = (const float*)d_in[11];
    const float* lng   = (const float*)d_in[12];
    const float* lnb   = (const float*)d_in[13];
    float* h = (float*)d_out;

    float *p_xh, *p_out, *p_f1, *p_watt;
    cudaGetSymbolAddress((void**)&p_xh,   g_xh);
    cudaGetSymbolAddress((void**)&p_out,  g_out);
    cudaGetSymbolAddress((void**)&p_f1,   g_f1);
    cudaGetSymbolAddress((void**)&p_watt, g_watt);

    // ---- folded attention weights for all layers (independent of h) ----
    watt_prep_kernel<<<dim3(2, NL), 256>>>(Wc, att_s, att_d);

    // ---- CSR build (once; reused across layers) ----
    zero_cnt_kernel<<<(N_NODES + 255) / 256, 256>>>();
    hist_kernel<<<(EN + 255) / 256, 256>>>(ei);
    scan1_kernel<<<SCAN_NB, 256>>>();
    scan2_kernel<<<1, 128>>>();
    scan3_kernel<<<SCAN_NB, 256>>>();
    scatter_kernel<<<(EN + 255) / 256, 256>>>(ei);

    const int GY = (N_NODES + 127) / 128;
    const int WG = (N_NODES * 32 + 255) / 256;   // warp-per-node grids

    // ---- embed: h = (x @ We + be) * 8 ----
    mma_gemm_kernel<1><<<dim3(1, GY), 256>>>(x, We, be, h,
                                             N_NODES, HID, IN_DIM,
                                             IN_DIM, HID, HID, 0, 8.0f);
    // scores for layer 0
    scores_kernel<<<WG, 256>>>(h, p_watt);

    for (int l = 0; l < NL; l++) {
        const float* Wc_l = Wc + (long)l * HID * HC;
        // fused softmax + aggregate -> g_xh as ah buffer
        agg_fused_kernel<<<WG, 256>>>(h, p_xh);
        // project per head: out[:, hd*64:+64] = ah[:, hd*64:+64] @ Wc_l[hd] + bc
        mma_gemm_kernel<0><<<dim3(NH, GY), 256>>>(p_xh, Wc_l, bc + l * HC, p_out,
                                                  N_NODES, CD, HID,
                                                  HC, HC, HC, CD, 0.f);
        // f1 = gelu(out @ W1[l] + b1[l])
        mma_gemm_kernel<2><<<dim3(DFF / 64, GY), 256>>>(p_out, W1 + (long)l * HC * DFF,
                                                        b1 + l * DFF, p_f1,
                                                        N_NODES, DFF, HC,
                                                        HC, DFF, DFF, 0, 0.f);
        // f2 = f1 @ W2[l] + b2[l]  (reuse g_xh as f2 buffer)
        mma_gemm_kernel<0><<<dim3(1, GY), 256>>>(p_f1, W2 + (long)l * DFF * HID,
                                                 b2 + l * HID, p_xh,
                                                 N_NODES, HID, DFF,
                                                 DFF, HID, HID, 0, 0.f);
        // h += layernorm(f2); fused scores for next layer
        const float* watt_next = (l + 1 < NL) ? (p_watt + (l + 1) * HID * 8) : nullptr;
        ln_kernel<<<WG, 256>>>(p_xh, lng + l * HID, lnb + l * HID, h, watt_next);
    }
    (void)in_sizes; (void)n_in; (void)out_size;
}